// round 14
// baseline (speedup 1.0000x reference)
#include <cuda_runtime.h>
#include <math.h>

#define B 8
#define D 512
#define T 4096
#define CD 64
#define CS 1024
#define NSCALES 4
#define NSPLIT 16
#define NROWS (B*D)
#define BT (B*T)
#define ZQ_ELEMS (B*D*T)                  // 16777216
#define CODES_ELEMS (B*NSCALES*T)         // 131072
#define LOSS_OFF (ZQ_ELEMS + CODES_ELEMS)
#define LOSS_MEAN_DENOM 2097152.0f        // B*CD*T

// ------------------------ scratch ------------------------
__device__ float g_residual[ZQ_ELEMS];        // 64MB
__device__ float g_zf[ZQ_ELEMS];              // 64MB (band-filtered residual)
__device__ float g_ze[B*CD*T];                // 8MB
__device__ float g_inv2[BT];                  // 2/||z_e(t)||
__device__ float g_WiT[NSCALES*D*CD];         // weight-normed in-proj, [d][c]
__device__ float g_WoT[NSCALES*CD*D];         // weight-normed out-proj, [c][d]
__device__ float g_cnp[NSCALES*CS*CD];        // normalized codebook, tile/pair-packed
__device__ float g_cnn[NSCALES*CS];           // ||cn_j||^2
__device__ float g_pbest[NSPLIT*BT];
__device__ int   g_pidx [NSPLIT*BT];
__device__ float g_partials[NSCALES*256];

// ------------------------ f32x2 helpers ------------------------
__device__ __forceinline__ void fma2(unsigned long long& acc,
                                     unsigned long long a, unsigned long long b) {
    asm("fma.rn.f32x2 %0, %1, %2, %0;" : "+l"(acc) : "l"(a), "l"(b));
}
__device__ __forceinline__ unsigned long long packf2(float lo, float hi) {
    unsigned long long r;
    asm("mov.b64 %0, {%1, %2};" : "=l"(r) : "f"(lo), "f"(hi));
    return r;
}
__device__ __forceinline__ float2 unpackf2(unsigned long long v) {
    float lo, hi;
    asm("mov.b64 {%0, %1}, %2;" : "=f"(lo), "=f"(hi) : "l"(v));
    return make_float2(lo, hi);
}

// ------------------------ complex helpers ------------------------
__device__ __forceinline__ float2 cadd(float2 a, float2 b){return make_float2(a.x+b.x, a.y+b.y);}
__device__ __forceinline__ float2 csub(float2 a, float2 b){return make_float2(a.x-b.x, a.y-b.y);}
__device__ __forceinline__ float2 cmul(float2 a, float2 b){
    return make_float2(a.x*b.x - a.y*b.y, a.x*b.y + a.y*b.x);}
__device__ __forceinline__ float2 cmulc(float2 a, float2 b){
    return make_float2(a.x*b.x + a.y*b.y, a.y*b.x - a.x*b.y);}
__device__ __forceinline__ float2 mulnegi(float2 a){return make_float2(a.y, -a.x);}
__device__ __forceinline__ float2 mulposi(float2 a){return make_float2(-a.y, a.x);}

// ------------------------ weight prep (R3 exact) ------------------------
__global__ void prep_weights_kernel(const float* __restrict__ v_in,
                                    const float* __restrict__ g_in,
                                    const float* __restrict__ v_out,
                                    const float* __restrict__ g_out,
                                    const float* __restrict__ codebook)
{
    int blk = blockIdx.x;
    int sc = blk / 1600;
    int r  = blk % 1600;
    int tid = threadIdx.x;
    __shared__ float red[4];

    const float* src; int n; float g; int kind;
    if (r < 64) { src = v_in + (size_t)(sc*64 + r)*512; n = 512; g = g_in[sc*64 + r]; kind = 0; }
    else if (r < 576) { int d = r-64; src = v_out + (size_t)(sc*512 + d)*64; n = 64; g = g_out[sc*512 + d]; kind = 1; }
    else { src = codebook + (size_t)(sc*1024 + (r-576))*64; n = 64; g = 1.0f; kind = 2; }

    float ss = 0.f;
    for (int i = tid; i < n; i += 128) { float v = src[i]; ss = fmaf(v, v, ss); }
    #pragma unroll
    for (int o = 16; o; o >>= 1) ss += __shfl_xor_sync(~0u, ss, o);
    if ((tid & 31) == 0) red[tid >> 5] = ss;
    __syncthreads();
    float tot = red[0] + red[1] + red[2] + red[3];
    float inv = g / fmaxf(sqrtf(tot), 1e-12f);

    if (kind == 0) {
        int c = r;
        for (int i = tid; i < n; i += 128)
            g_WiT[((size_t)sc*512 + i)*64 + c] = src[i] * inv;
    } else if (kind == 1) {
        int d = r - 64;
        for (int i = tid; i < n; i += 128)
            g_WoT[((size_t)sc*64 + i)*512 + d] = src[i] * inv;
    } else {
        int j = r - 576;
        float ss2 = 0.f;
        for (int i = tid; i < n; i += 128) {
            float v = src[i] * inv;
            size_t fidx = ((((size_t)(sc*32 + (j>>5))*64 + i)*8 + ((j&31)>>2))*4) + (j&3);
            g_cnp[fidx] = v;
            ss2 = fmaf(v, v, ss2);
        }
        #pragma unroll
        for (int o = 16; o; o >>= 1) ss2 += __shfl_xor_sync(~0u, ss2, o);
        __syncthreads();
        if ((tid & 31) == 0) red[tid >> 5] = ss2;
        __syncthreads();
        if (tid == 0) g_cnn[sc*1024 + j] = red[0] + red[1] + red[2] + red[3];
    }
}

// ------------------------ FFT band filter (radix-8, R11 exact) ------------------------
__global__ __launch_bounds__(512) void fft_filter_kernel(const float* __restrict__ zsrc, int use_z, int fl)
{
    __shared__ float2 s[4096];
    __shared__ float2 tw[2048];
    const float* src = use_z ? zsrc : g_residual;
    size_t roff = (size_t)blockIdx.x * 2 * T;
    const float* x0g = src + roff;
    const float* x1g = x0g + T;
    int tid = threadIdx.x;
    const float RC = 0.70710678118654752f;

    for (int i = tid; i < 4096; i += 512) s[i] = make_float2(x0g[i], x1g[i]);
    for (int k = tid; k < 2048; k += 512) {
        float sv, cv;
        sincospif((float)k * (-1.0f/2048.0f), &sv, &cv);
        tw[k] = make_float2(cv, sv);
    }
    __syncthreads();

    for (int logq = 9; logq >= 0; logq -= 3) {
        int q = 1 << logq;
        int p = tid;
        int j = p & (q - 1);
        int base = ((p >> logq) << (logq + 3)) | j;
        float2 x0 = s[base],       x1 = s[base+q],   x2 = s[base+2*q], x3 = s[base+3*q];
        float2 x4 = s[base+4*q],   x5 = s[base+5*q], x6 = s[base+6*q], x7 = s[base+7*q];
        float2 p0 = cadd(x0,x4), p1 = csub(x0,x4), p2 = cadd(x2,x6), p3 = mulnegi(csub(x2,x6));
        float2 E0 = cadd(p0,p2), E1 = cadd(p1,p3), E2 = csub(p0,p2), E3 = csub(p1,p3);
        float2 q0 = cadd(x1,x5), q1 = csub(x1,x5), q2 = cadd(x3,x7), q3 = mulnegi(csub(x3,x7));
        float2 O0 = cadd(q0,q2), O1 = cadd(q1,q3), O2 = csub(q0,q2), O3 = csub(q1,q3);
        float2 r1 = make_float2(RC*(O1.x+O1.y), RC*(O1.y-O1.x));
        float2 r2 = mulnegi(O2);
        float2 r3 = make_float2(RC*(O3.y-O3.x), -RC*(O3.x+O3.y));
        float2 y0 = cadd(E0,O0), y4 = csub(E0,O0);
        float2 y1 = cadd(E1,r1), y5 = csub(E1,r1);
        float2 y2 = cadd(E2,r2), y6 = csub(E2,r2);
        float2 y3 = cadd(E3,r3), y7 = csub(E3,r3);
        int e = j << (9 - logq);
        float2 w1 = tw[e], w2 = tw[2*e], w4 = tw[4*e];
        float2 w3 = cmul(w2,w1), w5 = cmul(w4,w1), w6 = cmul(w4,w2), w7 = cmul(w4,w3);
        s[base]       = y0;
        s[base+q]     = cmul(y1,w1);
        s[base+2*q]   = cmul(y2,w2);
        s[base+3*q]   = cmul(y3,w3);
        s[base+4*q]   = cmul(y4,w4);
        s[base+5*q]   = cmul(y5,w5);
        s[base+6*q]   = cmul(y6,w6);
        s[base+7*q]   = cmul(y7,w7);
        __syncthreads();
    }

    for (int p = tid; p < 4096; p += 512) {
        int k = ((p & 7) << 9) | (((p >> 3) & 7) << 6) | (((p >> 6) & 7) << 3) | ((p >> 9) & 7);
        if (!(k <= fl || k >= 4096 - fl)) s[p] = make_float2(0.f, 0.f);
    }
    __syncthreads();

    for (int logq = 0; logq <= 9; logq += 3) {
        int q = 1 << logq;
        int p = tid;
        int j = p & (q - 1);
        int base = ((p >> logq) << (logq + 3)) | j;
        int e = j << (9 - logq);
        float2 w1 = tw[e], w2 = tw[2*e], w4 = tw[4*e];
        float2 w3 = cmul(w2,w1), w5 = cmul(w4,w1), w6 = cmul(w4,w2), w7 = cmul(w4,w3);
        float2 x0 = s[base];
        float2 x1 = cmulc(s[base+q],   w1);
        float2 x2 = cmulc(s[base+2*q], w2);
        float2 x3 = cmulc(s[base+3*q], w3);
        float2 x4 = cmulc(s[base+4*q], w4);
        float2 x5 = cmulc(s[base+5*q], w5);
        float2 x6 = cmulc(s[base+6*q], w6);
        float2 x7 = cmulc(s[base+7*q], w7);
        float2 p0 = cadd(x0,x4), p1 = csub(x0,x4), p2 = cadd(x2,x6), p3 = mulposi(csub(x2,x6));
        float2 E0 = cadd(p0,p2), E1 = cadd(p1,p3), E2 = csub(p0,p2), E3 = csub(p1,p3);
        float2 q0 = cadd(x1,x5), q1 = csub(x1,x5), q2 = cadd(x3,x7), q3 = mulposi(csub(x3,x7));
        float2 O0 = cadd(q0,q2), O1 = cadd(q1,q3), O2 = csub(q0,q2), O3 = csub(q1,q3);
        float2 r1 = make_float2(RC*(O1.x-O1.y),  RC*(O1.x+O1.y));
        float2 r2 = mulposi(O2);
        float2 r3 = make_float2(-RC*(O3.x+O3.y), RC*(O3.x-O3.y));
        s[base]      = cadd(E0,O0);
        s[base+4*q]  = csub(E0,O0);
        s[base+q]    = cadd(E1,r1);
        s[base+5*q]  = csub(E1,r1);
        s[base+2*q]  = cadd(E2,r2);
        s[base+6*q]  = csub(E2,r2);
        s[base+3*q]  = cadd(E3,r3);
        s[base+7*q]  = csub(E3,r3);
        __syncthreads();
    }

    float* y0p = g_zf + roff;
    float* y1p = y0p + T;
    const float scl = 1.0f / 4096.0f;
    for (int i = tid; i < 4096; i += 512) {
        float2 v = s[i];
        y0p[i] = v.x * scl;
        y1p[i] = v.y * scl;
    }
}

// ------------------------ in_proj (512 thr, two t-groups; bit-identical chains) ------------------------
// Block tile 64c x 128t; group g = tid>>8 owns t in [g*64, g*64+64). Thread = 8c x 2t.
// Per-(c,t) d-ascending fmaf chain identical to the 256-thread version.
__global__ __launch_bounds__(512, 2) void in_proj_kernel(int sc, int use_zf, const float* __restrict__ b_in)
{
    __shared__ float zsm[32][128];   // 16KB
    __shared__ float wsm[32][64];    // 8KB
    __shared__ float red[128][8];    // 4KB
    const float* src = use_zf ? g_zf : g_residual;
    int b = blockIdx.y, t0 = blockIdx.x * 128;
    int tid = threadIdx.x;
    int g = tid >> 8, gtid = tid & 255;
    int tx = gtid & 31, ty = gtid >> 5;
    int tbase = g*64 + 2*tx;             // first of this thread's 2 t-columns

    unsigned long long acc[8];
    #pragma unroll
    for (int i = 0; i < 8; i++) acc[i] = 0ull;

    for (int d0 = 0; d0 < D; d0 += 32) {
        for (int i = tid; i < 32*128; i += 512) {
            int dd = i >> 7, tt = i & 127;
            zsm[dd][tt] = src[((size_t)(b*D + d0 + dd))*T + t0 + tt];
        }
        for (int i = tid; i < 32*64; i += 512) {
            int dd = i >> 6, c = i & 63;
            wsm[dd][c] = g_WiT[((size_t)sc*512 + d0 + dd)*64 + c];
        }
        __syncthreads();
        #pragma unroll 8
        for (int dd = 0; dd < 32; dd++) {
            unsigned long long z2 = *(const unsigned long long*)&zsm[dd][tbase];
            float4 wa = *(const float4*)&wsm[dd][8*ty];
            float4 wb = *(const float4*)&wsm[dd][8*ty + 4];
            fma2(acc[0], packf2(wa.x, wa.x), z2);
            fma2(acc[1], packf2(wa.y, wa.y), z2);
            fma2(acc[2], packf2(wa.z, wa.z), z2);
            fma2(acc[3], packf2(wa.w, wa.w), z2);
            fma2(acc[4], packf2(wb.x, wb.x), z2);
            fma2(acc[5], packf2(wb.y, wb.y), z2);
            fma2(acc[6], packf2(wb.z, wb.z), z2);
            fma2(acc[7], packf2(wb.w, wb.w), z2);
        }
        __syncthreads();
    }

    float ss0 = 0.f, ss1 = 0.f;
    #pragma unroll
    for (int cc = 0; cc < 8; cc++) {
        int c = 8*ty + cc;
        float bb = b_in[sc*CD + c];
        float2 v0 = unpackf2(acc[cc]);
        float2 st = make_float2(v0.x + bb, v0.y + bb);
        *(float2*)&g_ze[((size_t)(b*CD + c))*T + t0 + tbase] = st;
        ss0 = fmaf(st.x, st.x, ss0);
        ss1 = fmaf(st.y, st.y, ss1);
    }
    red[tbase + 0][ty] = ss0;
    red[tbase + 1][ty] = ss1;
    __syncthreads();
    if (tid < 128) {
        float s = 0.f;
        #pragma unroll
        for (int w = 0; w < 8; w++) s += red[tid][w];
        g_inv2[b*T + t0 + tid] = 2.0f / fmaxf(sqrtf(s), 1e-12f);
    }
}

// ------------------------ nearest-code argmax (R11 exact: c-tiled, occ 5) ------------------------
__global__ __launch_bounds__(128, 5) void argmax_kernel(int sc)
{
    __shared__ float zsh[32][128];           // 16KB (reused for reduction scratch)
    __shared__ ulonglong2 wsh[2][32][8];     // 8KB
    int b = blockIdx.y, split = blockIdx.z;
    int t0 = blockIdx.x * 128;
    int tid = threadIdx.x;
    int tx = tid & 31, ty = tid >> 5;
    int jt = ty >> 1;
    int qh = (ty & 1) * 4;

    unsigned long long acc[4][8];
    #pragma unroll
    for (int i = 0; i < 4; i++)
        #pragma unroll
        for (int m = 0; m < 8; m++) acc[i][m] = 0ull;

    const float4* p = (const float4*)(g_cnp + (size_t)(sc*32 + split*2)*2048);

    for (int ch = 0; ch < 2; ch++) {
        __syncthreads();
        for (int i = tid; i < 1024; i += 128) {
            int c = i >> 5, f4 = i & 31;
            ((float4*)&zsh[c][0])[f4] =
                *(const float4*)&g_ze[((size_t)(b*CD + ch*32 + c))*T + t0 + 4*f4];
        }
        for (int l = tid; l < 512; l += 128) {
            int sub = l >> 8, idx = l & 255;
            ((float4*)wsh)[l] = p[sub*512 + ch*256 + idx];
        }
        __syncthreads();

        #pragma unroll 4
        for (int cc = 0; cc < 32; cc++) {
            float4 zf = *(const float4*)&zsh[cc][4*tx];
            unsigned long long zz0 = packf2(zf.x, zf.x);
            unsigned long long zz1 = packf2(zf.y, zf.y);
            unsigned long long zz2 = packf2(zf.z, zf.z);
            unsigned long long zz3 = packf2(zf.w, zf.w);
            #pragma unroll
            for (int q = 0; q < 4; q++) {
                ulonglong2 w = wsh[jt][cc][qh + q];
                fma2(acc[0][2*q], w.x, zz0); fma2(acc[0][2*q+1], w.y, zz0);
                fma2(acc[1][2*q], w.x, zz1); fma2(acc[1][2*q+1], w.y, zz1);
                fma2(acc[2][2*q], w.x, zz2); fma2(acc[2][2*q+1], w.y, zz2);
                fma2(acc[3][2*q], w.x, zz3); fma2(acc[3][2*q+1], w.y, zz3);
            }
        }
    }

    float iv[4];
    #pragma unroll
    for (int i = 0; i < 4; i++) iv[i] = g_inv2[b*T + t0 + 4*tx + i];

    int jbase = split*64 + jt*32 + qh*4;
    const float* cnn = g_cnn + sc*CS + jbase;
    float best[4]; int bi[4];
    #pragma unroll
    for (int i = 0; i < 4; i++) { best[i] = -INFINITY; bi[i] = 0; }

    #pragma unroll
    for (int q = 0; q < 4; q++) {
        float n0 = cnn[4*q + 0], n1 = cnn[4*q + 1], n2 = cnn[4*q + 2], n3 = cnn[4*q + 3];
        #pragma unroll
        for (int i = 0; i < 4; i++) {
            float2 d0 = unpackf2(acc[i][2*q]);
            float2 d1 = unpackf2(acc[i][2*q+1]);
            float s0 = fmaf(d0.x, iv[i], -n0);
            float s1 = fmaf(d0.y, iv[i], -n1);
            float s2 = fmaf(d1.x, iv[i], -n2);
            float s3 = fmaf(d1.y, iv[i], -n3);
            int j0 = jbase + 4*q;
            if (s0 > best[i]) { best[i] = s0; bi[i] = j0; }
            if (s1 > best[i]) { best[i] = s1; bi[i] = j0 + 1; }
            if (s2 > best[i]) { best[i] = s2; bi[i] = j0 + 2; }
            if (s3 > best[i]) { best[i] = s3; bi[i] = j0 + 3; }
        }
    }

    __syncthreads();
    float* rb = &zsh[0][0];            // [128][4] floats
    int*   ri = (int*)&zsh[4][0];      // [128][4] ints (disjoint)
    #pragma unroll
    for (int i = 0; i < 4; i++) {
        rb[(4*tx + i)*4 + ty] = best[i];
        ri[(4*tx + i)*4 + ty] = bi[i];
    }
    __syncthreads();
    if (tid < 128) {
        float bv = -INFINITY; int bj = 0x7fffffff;
        #pragma unroll
        for (int k = 0; k < 4; k++) {
            float v = rb[tid*4 + k];
            int ix = ri[tid*4 + k];
            if (v > bv || (v == bv && ix < bj)) { bv = v; bj = ix; }
        }
        size_t gi = (size_t)split*BT + b*T + t0 + tid;
        g_pbest[gi] = bv;
        g_pidx[gi]  = bj;
    }
}

// ------------------------ split-combine + loss + out_proj + residual (R13 exact: 512 thr) ------------------------
__global__ __launch_bounds__(512, 2) void loss_outproj_kernel(int sc, int mode,
    const float* __restrict__ cb_s, const float* __restrict__ b_out_s,
    const float* __restrict__ z, float* __restrict__ zq_out, float* __restrict__ codes_out)
{
    extern __shared__ float smem[];
    float* cbs    = smem;                 // [64][128], XOR-swizzled columns
    float* wpool2 = smem + 8192;          // [2][64*64]
    int*   scodes = (int*)wpool2;         // [128]
    float* redp   = wpool2 + 128;         // [16]
    int b = blockIdx.y, t0 = blockIdx.x * 128;
    int tid = threadIdx.x;
    int g = tid >> 8, gtid = tid & 255;
    int tx = gtid & 31, ty = gtid >> 5;

    if (tid < 128) {
        int gi = b*T + t0 + tid;
        float bv = -INFINITY; int bj = 0;
        #pragma unroll
        for (int sp = 0; sp < NSPLIT; sp++) {
            float v = g_pbest[(size_t)sp*BT + gi];
            int ix = g_pidx[(size_t)sp*BT + gi];
            if (v > bv) { bv = v; bj = ix; }
        }
        scodes[tid] = bj;
        if (codes_out)
            codes_out[((size_t)(b*NSCALES + sc))*T + t0 + tid] = (float)bj;
    }
    __syncthreads();

    for (int i = tid; i < 64*128; i += 512) {
        int tt = i >> 6, c = i & 63;
        cbs[c*128 + (tt ^ ((c & 31) << 2))] = cb_s[scodes[tt]*64 + c];
    }
    __syncthreads();

    float ls = 0.f;
    for (int i = tid; i < 64*128; i += 512) {
        int c = i >> 7, tt = i & 127;
        float d = g_ze[((size_t)(b*CD + c))*T + t0 + tt] - cbs[c*128 + (tt ^ ((c & 31) << 2))];
        ls = fmaf(d, d, ls);
    }
    #pragma unroll
    for (int o = 16; o; o >>= 1) ls += __shfl_xor_sync(~0u, ls, o);
    if ((tid & 31) == 0) redp[tid >> 5] = ls;
    __syncthreads();
    if (tid == 0) {
        float tot = 0.f;
        #pragma unroll
        for (int w = 0; w < 16; w++) tot += redp[w];
        g_partials[sc*256 + b*32 + blockIdx.x] = tot;
    }

    float* wg = wpool2 + g*4096;
    for (int k8 = 0; k8 < 4; k8++) {
        int d0 = g*256 + k8*64;
        __syncthreads();
        for (int i = gtid; i < 64*64; i += 256) {
            int c = i >> 6, dd = i & 63;
            wg[c*64 + dd] = g_WoT[((size_t)sc*64 + c)*512 + d0 + dd];
        }
        __syncthreads();

        unsigned long long acc[8][2];
        #pragma unroll
        for (int i = 0; i < 8; i++) { acc[i][0] = 0ull; acc[i][1] = 0ull; }
        #pragma unroll 8
        for (int c = 0; c < 64; c++) {
            ulonglong2 cb2 = *(const ulonglong2*)&cbs[c*128 + ((4*tx) ^ ((c & 31) << 2))];
            float4 wa = *(const float4*)&wg[c*64 + 8*ty];
            float4 wb = *(const float4*)&wg[c*64 + 8*ty + 4];
            unsigned long long w0 = packf2(wa.x, wa.x), w1 = packf2(wa.y, wa.y);
            unsigned long long w2 = packf2(wa.z, wa.z), w3 = packf2(wa.w, wa.w);
            unsigned long long w4 = packf2(wb.x, wb.x), w5 = packf2(wb.y, wb.y);
            unsigned long long w6 = packf2(wb.z, wb.z), w7 = packf2(wb.w, wb.w);
            fma2(acc[0][0], w0, cb2.x); fma2(acc[0][1], w0, cb2.y);
            fma2(acc[1][0], w1, cb2.x); fma2(acc[1][1], w1, cb2.y);
            fma2(acc[2][0], w2, cb2.x); fma2(acc[2][1], w2, cb2.y);
            fma2(acc[3][0], w3, cb2.x); fma2(acc[3][1], w3, cb2.y);
            fma2(acc[4][0], w4, cb2.x); fma2(acc[4][1], w4, cb2.y);
            fma2(acc[5][0], w5, cb2.x); fma2(acc[5][1], w5, cb2.y);
            fma2(acc[6][0], w6, cb2.x); fma2(acc[6][1], w6, cb2.y);
            fma2(acc[7][0], w7, cb2.x); fma2(acc[7][1], w7, cb2.y);
        }

        #pragma unroll
        for (int k = 0; k < 8; k++) {
            int d = d0 + 8*ty + k;
            float bb = b_out_s[d];
            float2 u0 = unpackf2(acc[k][0]);
            float2 u1 = unpackf2(acc[k][1]);
            float4 v = make_float4(u0.x + bb, u0.y + bb, u1.x + bb, u1.y + bb);
            size_t base = ((size_t)(b*D + d))*T + t0 + 4*tx;
            if (mode == 0) {
                float4 zv = *(const float4*)&z[base];
                float4 r = make_float4(zv.x - v.x, zv.y - v.y, zv.z - v.z, zv.w - v.w);
                *(float4*)&g_residual[base] = r;
            } else if (mode == 1) {
                float4 r = *(const float4*)&g_residual[base];
                r.x -= v.x; r.y -= v.y; r.z -= v.z; r.w -= v.w;
                *(float4*)&g_residual[base] = r;
            } else {
                float4 zv = *(const float4*)&z[base];
                float4 r = *(const float4*)&g_residual[base];
                float4 o = make_float4(zv.x - r.x + v.x, zv.y - r.y + v.y,
                                       zv.z - r.z + v.z, zv.w - r.w + v.w);
                *(float4*)&zq_out[base] = o;
            }
        }
    }
}

// ------------------------ final loss reduce ------------------------
__global__ void reduce_loss_kernel(float* __restrict__ out_loss)
{
    __shared__ float s[1024];
    int tid = threadIdx.x;
    float v = 0.f;
    for (int i = tid; i < NSCALES*256; i += 1024) v += g_partials[i];
    s[tid] = v;
    __syncthreads();
    for (int h = 512; h; h >>= 1) {
        if (tid < h) s[tid] += s[tid + h];
        __syncthreads();
    }
    if (tid == 0) {
        float m = s[0] / LOSS_MEAN_DENOM;
        out_loss[0] = m;
        out_loss[1] = m;
    }
}

// ------------------------ launch ------------------------
extern "C" void kernel_launch(void* const* d_in, const int* in_sizes, int n_in,
                              void* d_out, int out_size)
{
    const float* z     = (const float*)d_in[0];
    const float* v_in  = (const float*)d_in[1];
    const float* g_in  = (const float*)d_in[2];
    const float* b_in  = (const float*)d_in[3];
    const float* cb    = (const float*)d_in[4];
    const float* v_out = (const float*)d_in[5];
    const float* g_out = (const float*)d_in[6];
    const float* b_out = (const float*)d_in[7];
    float* out = (float*)d_out;

    bool full = out_size >= (LOSS_OFF + 2);
    float* codes_out = full ? (out + ZQ_ELEMS) : nullptr;

    const int SMEM_LO = 65536;
    cudaFuncSetAttribute(loss_outproj_kernel,
                         cudaFuncAttributeMaxDynamicSharedMemorySize, SMEM_LO);

    prep_weights_kernel<<<NSCALES*1600, 128>>>(v_in, g_in, v_out, g_out, cb);

    const int scales[NSCALES] = {4, 2, 1, 1};
    for (int i = 0; i < NSCALES; i++) {
        int s = scales[i];
        int use_zf = (s > 1) ? 1 : 0;
        if (use_zf) {
            int fl = 2049 / s;
            fft_filter_kernel<<<NROWS/2, 512>>>(z, (i == 0) ? 1 : 0, fl);
        }
        in_proj_kernel<<<dim3(T/128, B), 512>>>(i, use_zf, b_in);
        argmax_kernel<<<dim3(T/128, B, NSPLIT), 128>>>(i);
        int mode = (i == 0) ? 0 : ((i == NSCALES-1) ? 2 : 1);
        loss_outproj_kernel<<<dim3(T/128, B), 512, SMEM_LO>>>(i, mode, cb + (size_t)i*CS*CD,
                                                              b_out + i*D, z, out, codes_out);
    }
    if (full) reduce_loss_kernel<<<1, 1024>>>(out + LOSS_OFF);
}

// round 15
// speedup vs baseline: 1.0506x; 1.0506x over previous
#include <cuda_runtime.h>
#include <math.h>

#define B 8
#define D 512
#define T 4096
#define CD 64
#define CS 1024
#define NSCALES 4
#define NSPLIT 16
#define NROWS (B*D)
#define BT (B*T)
#define ZQ_ELEMS (B*D*T)                  // 16777216
#define CODES_ELEMS (B*NSCALES*T)         // 131072
#define LOSS_OFF (ZQ_ELEMS + CODES_ELEMS)
#define LOSS_MEAN_DENOM 2097152.0f        // B*CD*T

// ------------------------ scratch ------------------------
__device__ float g_residual[ZQ_ELEMS];        // 64MB
__device__ float g_zf[ZQ_ELEMS];              // 64MB (band-filtered residual)
__device__ float g_ze[B*CD*T];                // 8MB
__device__ float g_inv2[BT];                  // 2/||z_e(t)||
__device__ float g_WiT[NSCALES*D*CD];         // weight-normed in-proj, [d][c]
__device__ float g_WoT[NSCALES*CD*D];         // weight-normed out-proj, [c][d]
__device__ float g_cnp[NSCALES*CS*CD];        // normalized codebook, tile/pair-packed
__device__ float g_cnn[NSCALES*CS];           // ||cn_j||^2
__device__ float g_pbest[NSPLIT*BT];
__device__ int   g_pidx [NSPLIT*BT];
__device__ float g_partials[NSCALES*256];

// ------------------------ f32x2 helpers ------------------------
__device__ __forceinline__ void fma2(unsigned long long& acc,
                                     unsigned long long a, unsigned long long b) {
    asm("fma.rn.f32x2 %0, %1, %2, %0;" : "+l"(acc) : "l"(a), "l"(b));
}
__device__ __forceinline__ unsigned long long packf2(float lo, float hi) {
    unsigned long long r;
    asm("mov.b64 %0, {%1, %2};" : "=l"(r) : "f"(lo), "f"(hi));
    return r;
}
__device__ __forceinline__ float2 unpackf2(unsigned long long v) {
    float lo, hi;
    asm("mov.b64 {%0, %1}, %2;" : "=f"(lo), "=f"(hi) : "l"(v));
    return make_float2(lo, hi);
}

// ------------------------ cp.async helpers ------------------------
__device__ __forceinline__ void cp16(void* dst_smem, const void* src) {
    unsigned u = (unsigned)__cvta_generic_to_shared(dst_smem);
    asm volatile("cp.async.cg.shared.global [%0], [%1], 16;" :: "r"(u), "l"(src));
}
#define CP_COMMIT() asm volatile("cp.async.commit_group;" ::: "memory")
#define CP_WAIT1()  asm volatile("cp.async.wait_group 1;" ::: "memory")
#define CP_WAIT0()  asm volatile("cp.async.wait_group 0;" ::: "memory")

// ------------------------ complex helpers ------------------------
__device__ __forceinline__ float2 cadd(float2 a, float2 b){return make_float2(a.x+b.x, a.y+b.y);}
__device__ __forceinline__ float2 csub(float2 a, float2 b){return make_float2(a.x-b.x, a.y-b.y);}
__device__ __forceinline__ float2 cmul(float2 a, float2 b){
    return make_float2(a.x*b.x - a.y*b.y, a.x*b.y + a.y*b.x);}
__device__ __forceinline__ float2 cmulc(float2 a, float2 b){
    return make_float2(a.x*b.x + a.y*b.y, a.y*b.x - a.x*b.y);}
__device__ __forceinline__ float2 mulnegi(float2 a){return make_float2(a.y, -a.x);}
__device__ __forceinline__ float2 mulposi(float2 a){return make_float2(-a.y, a.x);}

// ------------------------ weight prep (R3 exact) ------------------------
__global__ void prep_weights_kernel(const float* __restrict__ v_in,
                                    const float* __restrict__ g_in,
                                    const float* __restrict__ v_out,
                                    const float* __restrict__ g_out,
                                    const float* __restrict__ codebook)
{
    int blk = blockIdx.x;
    int sc = blk / 1600;
    int r  = blk % 1600;
    int tid = threadIdx.x;
    __shared__ float red[4];

    const float* src; int n; float g; int kind;
    if (r < 64) { src = v_in + (size_t)(sc*64 + r)*512; n = 512; g = g_in[sc*64 + r]; kind = 0; }
    else if (r < 576) { int d = r-64; src = v_out + (size_t)(sc*512 + d)*64; n = 64; g = g_out[sc*512 + d]; kind = 1; }
    else { src = codebook + (size_t)(sc*1024 + (r-576))*64; n = 64; g = 1.0f; kind = 2; }

    float ss = 0.f;
    for (int i = tid; i < n; i += 128) { float v = src[i]; ss = fmaf(v, v, ss); }
    #pragma unroll
    for (int o = 16; o; o >>= 1) ss += __shfl_xor_sync(~0u, ss, o);
    if ((tid & 31) == 0) red[tid >> 5] = ss;
    __syncthreads();
    float tot = red[0] + red[1] + red[2] + red[3];
    float inv = g / fmaxf(sqrtf(tot), 1e-12f);

    if (kind == 0) {
        int c = r;
        for (int i = tid; i < n; i += 128)
            g_WiT[((size_t)sc*512 + i)*64 + c] = src[i] * inv;
    } else if (kind == 1) {
        int d = r - 64;
        for (int i = tid; i < n; i += 128)
            g_WoT[((size_t)sc*64 + i)*512 + d] = src[i] * inv;
    } else {
        int j = r - 576;
        float ss2 = 0.f;
        for (int i = tid; i < n; i += 128) {
            float v = src[i] * inv;
            size_t fidx = ((((size_t)(sc*32 + (j>>5))*64 + i)*8 + ((j&31)>>2))*4) + (j&3);
            g_cnp[fidx] = v;
            ss2 = fmaf(v, v, ss2);
        }
        #pragma unroll
        for (int o = 16; o; o >>= 1) ss2 += __shfl_xor_sync(~0u, ss2, o);
        __syncthreads();
        if ((tid & 31) == 0) red[tid >> 5] = ss2;
        __syncthreads();
        if (tid == 0) g_cnn[sc*1024 + j] = red[0] + red[1] + red[2] + red[3];
    }
}

// ------------------------ FFT band filter (radix-8, R11 exact) ------------------------
__global__ __launch_bounds__(512) void fft_filter_kernel(const float* __restrict__ zsrc, int use_z, int fl)
{
    __shared__ float2 s[4096];
    __shared__ float2 tw[2048];
    const float* src = use_z ? zsrc : g_residual;
    size_t roff = (size_t)blockIdx.x * 2 * T;
    const float* x0g = src + roff;
    const float* x1g = x0g + T;
    int tid = threadIdx.x;
    const float RC = 0.70710678118654752f;

    for (int i = tid; i < 4096; i += 512) s[i] = make_float2(x0g[i], x1g[i]);
    for (int k = tid; k < 2048; k += 512) {
        float sv, cv;
        sincospif((float)k * (-1.0f/2048.0f), &sv, &cv);
        tw[k] = make_float2(cv, sv);
    }
    __syncthreads();

    for (int logq = 9; logq >= 0; logq -= 3) {
        int q = 1 << logq;
        int p = tid;
        int j = p & (q - 1);
        int base = ((p >> logq) << (logq + 3)) | j;
        float2 x0 = s[base],       x1 = s[base+q],   x2 = s[base+2*q], x3 = s[base+3*q];
        float2 x4 = s[base+4*q],   x5 = s[base+5*q], x6 = s[base+6*q], x7 = s[base+7*q];
        float2 p0 = cadd(x0,x4), p1 = csub(x0,x4), p2 = cadd(x2,x6), p3 = mulnegi(csub(x2,x6));
        float2 E0 = cadd(p0,p2), E1 = cadd(p1,p3), E2 = csub(p0,p2), E3 = csub(p1,p3);
        float2 q0 = cadd(x1,x5), q1 = csub(x1,x5), q2 = cadd(x3,x7), q3 = mulnegi(csub(x3,x7));
        float2 O0 = cadd(q0,q2), O1 = cadd(q1,q3), O2 = csub(q0,q2), O3 = csub(q1,q3);
        float2 r1 = make_float2(RC*(O1.x+O1.y), RC*(O1.y-O1.x));
        float2 r2 = mulnegi(O2);
        float2 r3 = make_float2(RC*(O3.y-O3.x), -RC*(O3.x+O3.y));
        float2 y0 = cadd(E0,O0), y4 = csub(E0,O0);
        float2 y1 = cadd(E1,r1), y5 = csub(E1,r1);
        float2 y2 = cadd(E2,r2), y6 = csub(E2,r2);
        float2 y3 = cadd(E3,r3), y7 = csub(E3,r3);
        int e = j << (9 - logq);
        float2 w1 = tw[e], w2 = tw[2*e], w4 = tw[4*e];
        float2 w3 = cmul(w2,w1), w5 = cmul(w4,w1), w6 = cmul(w4,w2), w7 = cmul(w4,w3);
        s[base]       = y0;
        s[base+q]     = cmul(y1,w1);
        s[base+2*q]   = cmul(y2,w2);
        s[base+3*q]   = cmul(y3,w3);
        s[base+4*q]   = cmul(y4,w4);
        s[base+5*q]   = cmul(y5,w5);
        s[base+6*q]   = cmul(y6,w6);
        s[base+7*q]   = cmul(y7,w7);
        __syncthreads();
    }

    for (int p = tid; p < 4096; p += 512) {
        int k = ((p & 7) << 9) | (((p >> 3) & 7) << 6) | (((p >> 6) & 7) << 3) | ((p >> 9) & 7);
        if (!(k <= fl || k >= 4096 - fl)) s[p] = make_float2(0.f, 0.f);
    }
    __syncthreads();

    for (int logq = 0; logq <= 9; logq += 3) {
        int q = 1 << logq;
        int p = tid;
        int j = p & (q - 1);
        int base = ((p >> logq) << (logq + 3)) | j;
        int e = j << (9 - logq);
        float2 w1 = tw[e], w2 = tw[2*e], w4 = tw[4*e];
        float2 w3 = cmul(w2,w1), w5 = cmul(w4,w1), w6 = cmul(w4,w2), w7 = cmul(w4,w3);
        float2 x0 = s[base];
        float2 x1 = cmulc(s[base+q],   w1);
        float2 x2 = cmulc(s[base+2*q], w2);
        float2 x3 = cmulc(s[base+3*q], w3);
        float2 x4 = cmulc(s[base+4*q], w4);
        float2 x5 = cmulc(s[base+5*q], w5);
        float2 x6 = cmulc(s[base+6*q], w6);
        float2 x7 = cmulc(s[base+7*q], w7);
        float2 p0 = cadd(x0,x4), p1 = csub(x0,x4), p2 = cadd(x2,x6), p3 = mulposi(csub(x2,x6));
        float2 E0 = cadd(p0,p2), E1 = cadd(p1,p3), E2 = csub(p0,p2), E3 = csub(p1,p3);
        float2 q0 = cadd(x1,x5), q1 = csub(x1,x5), q2 = cadd(x3,x7), q3 = mulposi(csub(x3,x7));
        float2 O0 = cadd(q0,q2), O1 = cadd(q1,q3), O2 = csub(q0,q2), O3 = csub(q1,q3);
        float2 r1 = make_float2(RC*(O1.x-O1.y),  RC*(O1.x+O1.y));
        float2 r2 = mulposi(O2);
        float2 r3 = make_float2(-RC*(O3.x+O3.y), RC*(O3.x-O3.y));
        s[base]      = cadd(E0,O0);
        s[base+4*q]  = csub(E0,O0);
        s[base+q]    = cadd(E1,r1);
        s[base+5*q]  = csub(E1,r1);
        s[base+2*q]  = cadd(E2,r2);
        s[base+6*q]  = csub(E2,r2);
        s[base+3*q]  = cadd(E3,r3);
        s[base+7*q]  = csub(E3,r3);
        __syncthreads();
    }

    float* y0p = g_zf + roff;
    float* y1p = y0p + T;
    const float scl = 1.0f / 4096.0f;
    for (int i = tid; i < 4096; i += 512) {
        float2 v = s[i];
        y0p[i] = v.x * scl;
        y1p[i] = v.y * scl;
    }
}

// ------------------------ in_proj (R13/R3 exact: 256 thr) ------------------------
__global__ __launch_bounds__(256) void in_proj_kernel(int sc, int use_zf, const float* __restrict__ b_in)
{
    __shared__ float zsm[32][128];   // 16KB
    __shared__ float wsm[32][64];    // 8KB
    __shared__ float red[128][8];    // 4KB
    const float* src = use_zf ? g_zf : g_residual;
    int b = blockIdx.y, t0 = blockIdx.x * 128;
    int tid = threadIdx.x;
    int tx = tid & 31, ty = tid >> 5;

    unsigned long long acc[8][2];
    #pragma unroll
    for (int i = 0; i < 8; i++) { acc[i][0] = 0ull; acc[i][1] = 0ull; }

    for (int d0 = 0; d0 < D; d0 += 32) {
        for (int i = tid; i < 32*128; i += 256) {
            int dd = i >> 7, tt = i & 127;
            zsm[dd][tt] = src[((size_t)(b*D + d0 + dd))*T + t0 + tt];
        }
        for (int i = tid; i < 32*64; i += 256) {
            int dd = i >> 6, c = i & 63;
            wsm[dd][c] = g_WiT[((size_t)sc*512 + d0 + dd)*64 + c];
        }
        __syncthreads();
        #pragma unroll 8
        for (int dd = 0; dd < 32; dd++) {
            ulonglong2 z2 = *(const ulonglong2*)&zsm[dd][4*tx];
            float4 wa = *(const float4*)&wsm[dd][8*ty];
            float4 wb = *(const float4*)&wsm[dd][8*ty + 4];
            unsigned long long w0 = packf2(wa.x, wa.x), w1 = packf2(wa.y, wa.y);
            unsigned long long w2 = packf2(wa.z, wa.z), w3 = packf2(wa.w, wa.w);
            unsigned long long w4 = packf2(wb.x, wb.x), w5 = packf2(wb.y, wb.y);
            unsigned long long w6 = packf2(wb.z, wb.z), w7 = packf2(wb.w, wb.w);
            fma2(acc[0][0], w0, z2.x); fma2(acc[0][1], w0, z2.y);
            fma2(acc[1][0], w1, z2.x); fma2(acc[1][1], w1, z2.y);
            fma2(acc[2][0], w2, z2.x); fma2(acc[2][1], w2, z2.y);
            fma2(acc[3][0], w3, z2.x); fma2(acc[3][1], w3, z2.y);
            fma2(acc[4][0], w4, z2.x); fma2(acc[4][1], w4, z2.y);
            fma2(acc[5][0], w5, z2.x); fma2(acc[5][1], w5, z2.y);
            fma2(acc[6][0], w6, z2.x); fma2(acc[6][1], w6, z2.y);
            fma2(acc[7][0], w7, z2.x); fma2(acc[7][1], w7, z2.y);
        }
        __syncthreads();
    }

    float ss0 = 0.f, ss1 = 0.f, ss2 = 0.f, ss3 = 0.f;
    #pragma unroll
    for (int cc = 0; cc < 8; cc++) {
        int c = 8*ty + cc;
        float bb = b_in[sc*CD + c];
        float2 v0 = unpackf2(acc[cc][0]);
        float2 v1 = unpackf2(acc[cc][1]);
        float4 st = make_float4(v0.x + bb, v0.y + bb, v1.x + bb, v1.y + bb);
        *(float4*)&g_ze[((size_t)(b*CD + c))*T + t0 + 4*tx] = st;
        ss0 = fmaf(st.x, st.x, ss0);
        ss1 = fmaf(st.y, st.y, ss1);
        ss2 = fmaf(st.z, st.z, ss2);
        ss3 = fmaf(st.w, st.w, ss3);
    }
    red[4*tx + 0][ty] = ss0;
    red[4*tx + 1][ty] = ss1;
    red[4*tx + 2][ty] = ss2;
    red[4*tx + 3][ty] = ss3;
    __syncthreads();
    if (tid < 128) {
        float s = 0.f;
        #pragma unroll
        for (int w = 0; w < 8; w++) s += red[tid][w];
        g_inv2[b*T + t0 + tid] = 2.0f / fmaxf(sqrtf(s), 1e-12f);
    }
}

// ------------------------ nearest-code argmax (c-tiled + cp.async double-buffer) ------------------------
// Same tiles, values and accumulation order as R11; staging via two cp.async groups
// so half-1's loads overlap half-0's compute.
__global__ __launch_bounds__(128, 4) void argmax_kernel(int sc)
{
    __shared__ float zsh[2][32][128];        // 32KB (half 0 reused for reduction scratch)
    __shared__ ulonglong2 wsh[2][2][32][8];  // 16KB
    int b = blockIdx.y, split = blockIdx.z;
    int t0 = blockIdx.x * 128;
    int tid = threadIdx.x;
    int tx = tid & 31, ty = tid >> 5;
    int jt = ty >> 1;
    int qh = (ty & 1) * 4;

    const float4* p = (const float4*)(g_cnp + (size_t)(sc*32 + split*2)*2048);

    #pragma unroll
    for (int ch = 0; ch < 2; ch++) {
        for (int i = tid; i < 1024; i += 128) {
            int c = i >> 5, f4 = i & 31;
            cp16(&((float4*)&zsh[ch][c][0])[f4],
                 (const float4*)&g_ze[((size_t)(b*CD + ch*32 + c))*T + t0 + 4*f4]);
        }
        for (int l = tid; l < 512; l += 128) {
            int sub = l >> 8, idx = l & 255;
            cp16(&((float4*)&wsh[ch][0][0][0])[l], &p[sub*512 + ch*256 + idx]);
        }
        CP_COMMIT();
    }

    unsigned long long acc[4][8];
    #pragma unroll
    for (int i = 0; i < 4; i++)
        #pragma unroll
        for (int m = 0; m < 8; m++) acc[i][m] = 0ull;

    CP_WAIT1();
    __syncthreads();

    #pragma unroll
    for (int ch = 0; ch < 2; ch++) {
        if (ch == 1) { CP_WAIT0(); __syncthreads(); }
        #pragma unroll 4
        for (int cc = 0; cc < 32; cc++) {
            float4 zf = *(const float4*)&zsh[ch][cc][4*tx];
            unsigned long long zz0 = packf2(zf.x, zf.x);
            unsigned long long zz1 = packf2(zf.y, zf.y);
            unsigned long long zz2 = packf2(zf.z, zf.z);
            unsigned long long zz3 = packf2(zf.w, zf.w);
            #pragma unroll
            for (int q = 0; q < 4; q++) {
                ulonglong2 w = wsh[ch][jt][cc][qh + q];
                fma2(acc[0][2*q], w.x, zz0); fma2(acc[0][2*q+1], w.y, zz0);
                fma2(acc[1][2*q], w.x, zz1); fma2(acc[1][2*q+1], w.y, zz1);
                fma2(acc[2][2*q], w.x, zz2); fma2(acc[2][2*q+1], w.y, zz2);
                fma2(acc[3][2*q], w.x, zz3); fma2(acc[3][2*q+1], w.y, zz3);
            }
        }
    }

    float iv[4];
    #pragma unroll
    for (int i = 0; i < 4; i++) iv[i] = g_inv2[b*T + t0 + 4*tx + i];

    int jbase = split*64 + jt*32 + qh*4;
    const float* cnn = g_cnn + sc*CS + jbase;
    float best[4]; int bi[4];
    #pragma unroll
    for (int i = 0; i < 4; i++) { best[i] = -INFINITY; bi[i] = 0; }

    #pragma unroll
    for (int q = 0; q < 4; q++) {
        float n0 = cnn[4*q + 0], n1 = cnn[4*q + 1], n2 = cnn[4*q + 2], n3 = cnn[4*q + 3];
        #pragma unroll
        for (int i = 0; i < 4; i++) {
            float2 d0 = unpackf2(acc[i][2*q]);
            float2 d1 = unpackf2(acc[i][2*q+1]);
            float s0 = fmaf(d0.x, iv[i], -n0);
            float s1 = fmaf(d0.y, iv[i], -n1);
            float s2 = fmaf(d1.x, iv[i], -n2);
            float s3 = fmaf(d1.y, iv[i], -n3);
            int j0 = jbase + 4*q;
            if (s0 > best[i]) { best[i] = s0; bi[i] = j0; }
            if (s1 > best[i]) { best[i] = s1; bi[i] = j0 + 1; }
            if (s2 > best[i]) { best[i] = s2; bi[i] = j0 + 2; }
            if (s3 > best[i]) { best[i] = s3; bi[i] = j0 + 3; }
        }
    }

    __syncthreads();
    float* rb = &zsh[0][0][0];            // [128][4] floats
    int*   ri = (int*)&zsh[0][4][0];      // [128][4] ints (disjoint)
    #pragma unroll
    for (int i = 0; i < 4; i++) {
        rb[(4*tx + i)*4 + ty] = best[i];
        ri[(4*tx + i)*4 + ty] = bi[i];
    }
    __syncthreads();
    if (tid < 128) {
        float bv = -INFINITY; int bj = 0x7fffffff;
        #pragma unroll
        for (int k = 0; k < 4; k++) {
            float v = rb[tid*4 + k];
            int ix = ri[tid*4 + k];
            if (v > bv || (v == bv && ix < bj)) { bv = v; bj = ix; }
        }
        size_t gi = (size_t)split*BT + b*T + t0 + tid;
        g_pbest[gi] = bv;
        g_pidx[gi]  = bj;
    }
}

// ------------------------ split-combine + loss + out_proj + residual (R13 exact: 512 thr) ------------------------
__global__ __launch_bounds__(512, 2) void loss_outproj_kernel(int sc, int mode,
    const float* __restrict__ cb_s, const float* __restrict__ b_out_s,
    const float* __restrict__ z, float* __restrict__ zq_out, float* __restrict__ codes_out)
{
    extern __shared__ float smem[];
    float* cbs    = smem;                 // [64][128], XOR-swizzled columns
    float* wpool2 = smem + 8192;          // [2][64*64]
    int*   scodes = (int*)wpool2;         // [128]
    float* redp   = wpool2 + 128;         // [16]
    int b = blockIdx.y, t0 = blockIdx.x * 128;
    int tid = threadIdx.x;
    int g = tid >> 8, gtid = tid & 255;
    int tx = gtid & 31, ty = gtid >> 5;

    if (tid < 128) {
        int gi = b*T + t0 + tid;
        float bv = -INFINITY; int bj = 0;
        #pragma unroll
        for (int sp = 0; sp < NSPLIT; sp++) {
            float v = g_pbest[(size_t)sp*BT + gi];
            int ix = g_pidx[(size_t)sp*BT + gi];
            if (v > bv) { bv = v; bj = ix; }
        }
        scodes[tid] = bj;
        if (codes_out)
            codes_out[((size_t)(b*NSCALES + sc))*T + t0 + tid] = (float)bj;
    }
    __syncthreads();

    for (int i = tid; i < 64*128; i += 512) {
        int tt = i >> 6, c = i & 63;
        cbs[c*128 + (tt ^ ((c & 31) << 2))] = cb_s[scodes[tt]*64 + c];
    }
    __syncthreads();

    float ls = 0.f;
    for (int i = tid; i < 64*128; i += 512) {
        int c = i >> 7, tt = i & 127;
        float d = g_ze[((size_t)(b*CD + c))*T + t0 + tt] - cbs[c*128 + (tt ^ ((c & 31) << 2))];
        ls = fmaf(d, d, ls);
    }
    #pragma unroll
    for (int o = 16; o; o >>= 1) ls += __shfl_xor_sync(~0u, ls, o);
    if ((tid & 31) == 0) redp[tid >> 5] = ls;
    __syncthreads();
    if (tid == 0) {
        float tot = 0.f;
        #pragma unroll
        for (int w = 0; w < 16; w++) tot += redp[w];
        g_partials[sc*256 + b*32 + blockIdx.x] = tot;
    }

    float* wg = wpool2 + g*4096;
    for (int k8 = 0; k8 < 4; k8++) {
        int d0 = g*256 + k8*64;
        __syncthreads();
        for (int i = gtid; i < 64*64; i += 256) {
            int c = i >> 6, dd = i & 63;
            wg[c*64 + dd] = g_WoT[((size_t)sc*64 + c)*512 + d0 + dd];
        }
        __syncthreads();

        unsigned long long acc[8][2];
        #pragma unroll
        for (int i = 0; i < 8; i++) { acc[i][0] = 0ull; acc[i][1] = 0ull; }
        #pragma unroll 8
        for (int c = 0; c < 64; c++) {
            ulonglong2 cb2 = *(const ulonglong2*)&cbs[c*128 + ((4*tx) ^ ((c & 31) << 2))];
            float4 wa = *(const float4*)&wg[c*64 + 8*ty];
            float4 wb = *(const float4*)&wg[c*64 + 8*ty + 4];
            unsigned long long w0 = packf2(wa.x, wa.x), w1 = packf2(wa.y, wa.y);
            unsigned long long w2 = packf2(wa.z, wa.z), w3 = packf2(wa.w, wa.w);
            unsigned long long w4 = packf2(wb.x, wb.x), w5 = packf2(wb.y, wb.y);
            unsigned long long w6 = packf2(wb.z, wb.z), w7 = packf2(wb.w, wb.w);
            fma2(acc[0][0], w0, cb2.x); fma2(acc[0][1], w0, cb2.y);
            fma2(acc[1][0], w1, cb2.x); fma2(acc[1][1], w1, cb2.y);
            fma2(acc[2][0], w2, cb2.x); fma2(acc[2][1], w2, cb2.y);
            fma2(acc[3][0], w3, cb2.x); fma2(acc[3][1], w3, cb2.y);
            fma2(acc[4][0], w4, cb2.x); fma2(acc[4][1], w4, cb2.y);
            fma2(acc[5][0], w5, cb2.x); fma2(acc[5][1], w5, cb2.y);
            fma2(acc[6][0], w6, cb2.x); fma2(acc[6][1], w6, cb2.y);
            fma2(acc[7][0], w7, cb2.x); fma2(acc[7][1], w7, cb2.y);
        }

        #pragma unroll
        for (int k = 0; k < 8; k++) {
            int d = d0 + 8*ty + k;
            float bb = b_out_s[d];
            float2 u0 = unpackf2(acc[k][0]);
            float2 u1 = unpackf2(acc[k][1]);
            float4 v = make_float4(u0.x + bb, u0.y + bb, u1.x + bb, u1.y + bb);
            size_t base = ((size_t)(b*D + d))*T + t0 + 4*tx;
            if (mode == 0) {
                float4 zv = *(const float4*)&z[base];
                float4 r = make_float4(zv.x - v.x, zv.y - v.y, zv.z - v.z, zv.w - v.w);
                *(float4*)&g_residual[base] = r;
            } else if (mode == 1) {
                float4 r = *(const float4*)&g_residual[base];
                r.x -= v.x; r.y -= v.y; r.z -= v.z; r.w -= v.w;
                *(float4*)&g_residual[base] = r;
            } else {
                float4 zv = *(const float4*)&z[base];
                float4 r = *(const float4*)&g_residual[base];
                float4 o = make_float4(zv.x - r.x + v.x, zv.y - r.y + v.y,
                                       zv.z - r.z + v.z, zv.w - r.w + v.w);
                *(float4*)&zq_out[base] = o;
            }
        }
    }
}

// ------------------------ final loss reduce ------------------------
__global__ void reduce_loss_kernel(float* __restrict__ out_loss)
{
    __shared__ float s[1024];
    int tid = threadIdx.x;
    float v = 0.f;
    for (int i = tid; i < NSCALES*256; i += 1024) v += g_partials[i];
    s[tid] = v;
    __syncthreads();
    for (int h = 512; h; h >>= 1) {
        if (tid < h) s[tid] += s[tid + h];
        __syncthreads();
    }
    if (tid == 0) {
        float m = s[0] / LOSS_MEAN_DENOM;
        out_loss[0] = m;
        out_loss[1] = m;
    }
}

// ------------------------ launch ------------------------
extern "C" void kernel_launch(void* const* d_in, const int* in_sizes, int n_in,
                              void* d_out, int out_size)
{
    const float* z     = (const float*)d_in[0];
    const float* v_in  = (const float*)d_in[1];
    const float* g_in  = (const float*)d_in[2];
    const float* b_in  = (const float*)d_in[3];
    const float* cb    = (const float*)d_in[4];
    const float* v_out = (const float*)d_in[5];
    const float* g_out = (const float*)d_in[6];
    const float* b_out = (const float*)d_in[7];
    float* out = (float*)d_out;

    bool full = out_size >= (LOSS_OFF + 2);
    float* codes_out = full ? (out + ZQ_ELEMS) : nullptr;

    const int SMEM_LO = 65536;
    cudaFuncSetAttribute(loss_outproj_kernel,
                         cudaFuncAttributeMaxDynamicSharedMemorySize, SMEM_LO);

    prep_weights_kernel<<<NSCALES*1600, 128>>>(v_in, g_in, v_out, g_out, cb);

    const int scales[NSCALES] = {4, 2, 1, 1};
    for (int i = 0; i < NSCALES; i++) {
        int s = scales[i];
        int use_zf = (s > 1) ? 1 : 0;
        if (use_zf) {
            int fl = 2049 / s;
            fft_filter_kernel<<<NROWS/2, 512>>>(z, (i == 0) ? 1 : 0, fl);
        }
        in_proj_kernel<<<dim3(T/128, B), 256>>>(i, use_zf, b_in);
        argmax_kernel<<<dim3(T/128, B, NSPLIT), 128>>>(i);
        int mode = (i == 0) ? 0 : ((i == NSCALES-1) ? 2 : 1);
        loss_outproj_kernel<<<dim3(T/128, B), 512, SMEM_LO>>>(i, mode, cb + (size_t)i*CS*CD,
                                                              b_out + i*D, z, out, codes_out);
    }
    if (full) reduce_loss_kernel<<<1, 1024>>>(out + LOSS_OFF);
}

// round 16
// speedup vs baseline: 1.1158x; 1.0620x over previous
#include <cuda_runtime.h>
#include <math.h>

#define B 8
#define D 512
#define T 4096
#define CD 64
#define CS 1024
#define NSCALES 4
#define NSPLIT 16
#define NROWS (B*D)
#define BT (B*T)
#define ZQ_ELEMS (B*D*T)                  // 16777216
#define CODES_ELEMS (B*NSCALES*T)         // 131072
#define LOSS_OFF (ZQ_ELEMS + CODES_ELEMS)
#define LOSS_MEAN_DENOM 2097152.0f        // B*CD*T

// ------------------------ scratch ------------------------
__device__ float g_residual[ZQ_ELEMS];        // 64MB
__device__ float g_zf[ZQ_ELEMS];              // 64MB (band-filtered residual)
__device__ float g_ze[B*CD*T];                // 8MB
__device__ float g_inv2[BT];                  // 2/||z_e(t)||
__device__ float g_WiT[NSCALES*D*CD];         // weight-normed in-proj, [d][c]
__device__ float g_WoT[NSCALES*CD*D];         // weight-normed out-proj, [c][d]
__device__ float g_cnp[NSCALES*CS*CD];        // normalized codebook, tile/pair-packed
__device__ float g_cnn[NSCALES*CS];           // ||cn_j||^2
__device__ float g_pbest[NSPLIT*BT];
__device__ int   g_pidx [NSPLIT*BT];
__device__ float g_partials[NSCALES*256];

// ------------------------ f32x2 helpers ------------------------
__device__ __forceinline__ void fma2(unsigned long long& acc,
                                     unsigned long long a, unsigned long long b) {
    asm("fma.rn.f32x2 %0, %1, %2, %0;" : "+l"(acc) : "l"(a), "l"(b));
}
__device__ __forceinline__ unsigned long long packf2(float lo, float hi) {
    unsigned long long r;
    asm("mov.b64 %0, {%1, %2};" : "=l"(r) : "f"(lo), "f"(hi));
    return r;
}
__device__ __forceinline__ float2 unpackf2(unsigned long long v) {
    float lo, hi;
    asm("mov.b64 {%0, %1}, %2;" : "=f"(lo), "=f"(hi) : "l"(v));
    return make_float2(lo, hi);
}

// ------------------------ cp.async helpers ------------------------
__device__ __forceinline__ void cp16(void* dst_smem, const void* src) {
    unsigned u = (unsigned)__cvta_generic_to_shared(dst_smem);
    asm volatile("cp.async.cg.shared.global [%0], [%1], 16;" :: "r"(u), "l"(src));
}
#define CP_COMMIT() asm volatile("cp.async.commit_group;" ::: "memory")
#define CP_WAIT1()  asm volatile("cp.async.wait_group 1;" ::: "memory")
#define CP_WAIT0()  asm volatile("cp.async.wait_group 0;" ::: "memory")

// ------------------------ complex helpers ------------------------
__device__ __forceinline__ float2 cadd(float2 a, float2 b){return make_float2(a.x+b.x, a.y+b.y);}
__device__ __forceinline__ float2 csub(float2 a, float2 b){return make_float2(a.x-b.x, a.y-b.y);}
__device__ __forceinline__ float2 cmul(float2 a, float2 b){
    return make_float2(a.x*b.x - a.y*b.y, a.x*b.y + a.y*b.x);}
__device__ __forceinline__ float2 cmulc(float2 a, float2 b){
    return make_float2(a.x*b.x + a.y*b.y, a.y*b.x - a.x*b.y);}
__device__ __forceinline__ float2 mulnegi(float2 a){return make_float2(a.y, -a.x);}
__device__ __forceinline__ float2 mulposi(float2 a){return make_float2(-a.y, a.x);}

// ------------------------ weight prep (R3 exact) ------------------------
__global__ void prep_weights_kernel(const float* __restrict__ v_in,
                                    const float* __restrict__ g_in,
                                    const float* __restrict__ v_out,
                                    const float* __restrict__ g_out,
                                    const float* __restrict__ codebook)
{
    int blk = blockIdx.x;
    int sc = blk / 1600;
    int r  = blk % 1600;
    int tid = threadIdx.x;
    __shared__ float red[4];

    const float* src; int n; float g; int kind;
    if (r < 64) { src = v_in + (size_t)(sc*64 + r)*512; n = 512; g = g_in[sc*64 + r]; kind = 0; }
    else if (r < 576) { int d = r-64; src = v_out + (size_t)(sc*512 + d)*64; n = 64; g = g_out[sc*512 + d]; kind = 1; }
    else { src = codebook + (size_t)(sc*1024 + (r-576))*64; n = 64; g = 1.0f; kind = 2; }

    float ss = 0.f;
    for (int i = tid; i < n; i += 128) { float v = src[i]; ss = fmaf(v, v, ss); }
    #pragma unroll
    for (int o = 16; o; o >>= 1) ss += __shfl_xor_sync(~0u, ss, o);
    if ((tid & 31) == 0) red[tid >> 5] = ss;
    __syncthreads();
    float tot = red[0] + red[1] + red[2] + red[3];
    float inv = g / fmaxf(sqrtf(tot), 1e-12f);

    if (kind == 0) {
        int c = r;
        for (int i = tid; i < n; i += 128)
            g_WiT[((size_t)sc*512 + i)*64 + c] = src[i] * inv;
    } else if (kind == 1) {
        int d = r - 64;
        for (int i = tid; i < n; i += 128)
            g_WoT[((size_t)sc*64 + i)*512 + d] = src[i] * inv;
    } else {
        int j = r - 576;
        float ss2 = 0.f;
        for (int i = tid; i < n; i += 128) {
            float v = src[i] * inv;
            size_t fidx = ((((size_t)(sc*32 + (j>>5))*64 + i)*8 + ((j&31)>>2))*4) + (j&3);
            g_cnp[fidx] = v;
            ss2 = fmaf(v, v, ss2);
        }
        #pragma unroll
        for (int o = 16; o; o >>= 1) ss2 += __shfl_xor_sync(~0u, ss2, o);
        __syncthreads();
        if ((tid & 31) == 0) red[tid >> 5] = ss2;
        __syncthreads();
        if (tid == 0) g_cnn[sc*1024 + j] = red[0] + red[1] + red[2] + red[3];
    }
}

// ------------------------ FFT band filter (radix-8, R11 exact) ------------------------
__global__ __launch_bounds__(512) void fft_filter_kernel(const float* __restrict__ zsrc, int use_z, int fl)
{
    __shared__ float2 s[4096];
    __shared__ float2 tw[2048];
    const float* src = use_z ? zsrc : g_residual;
    size_t roff = (size_t)blockIdx.x * 2 * T;
    const float* x0g = src + roff;
    const float* x1g = x0g + T;
    int tid = threadIdx.x;
    const float RC = 0.70710678118654752f;

    for (int i = tid; i < 4096; i += 512) s[i] = make_float2(x0g[i], x1g[i]);
    for (int k = tid; k < 2048; k += 512) {
        float sv, cv;
        sincospif((float)k * (-1.0f/2048.0f), &sv, &cv);
        tw[k] = make_float2(cv, sv);
    }
    __syncthreads();

    for (int logq = 9; logq >= 0; logq -= 3) {
        int q = 1 << logq;
        int p = tid;
        int j = p & (q - 1);
        int base = ((p >> logq) << (logq + 3)) | j;
        float2 x0 = s[base],       x1 = s[base+q],   x2 = s[base+2*q], x3 = s[base+3*q];
        float2 x4 = s[base+4*q],   x5 = s[base+5*q], x6 = s[base+6*q], x7 = s[base+7*q];
        float2 p0 = cadd(x0,x4), p1 = csub(x0,x4), p2 = cadd(x2,x6), p3 = mulnegi(csub(x2,x6));
        float2 E0 = cadd(p0,p2), E1 = cadd(p1,p3), E2 = csub(p0,p2), E3 = csub(p1,p3);
        float2 q0 = cadd(x1,x5), q1 = csub(x1,x5), q2 = cadd(x3,x7), q3 = mulnegi(csub(x3,x7));
        float2 O0 = cadd(q0,q2), O1 = cadd(q1,q3), O2 = csub(q0,q2), O3 = csub(q1,q3);
        float2 r1 = make_float2(RC*(O1.x+O1.y), RC*(O1.y-O1.x));
        float2 r2 = mulnegi(O2);
        float2 r3 = make_float2(RC*(O3.y-O3.x), -RC*(O3.x+O3.y));
        float2 y0 = cadd(E0,O0), y4 = csub(E0,O0);
        float2 y1 = cadd(E1,r1), y5 = csub(E1,r1);
        float2 y2 = cadd(E2,r2), y6 = csub(E2,r2);
        float2 y3 = cadd(E3,r3), y7 = csub(E3,r3);
        int e = j << (9 - logq);
        float2 w1 = tw[e], w2 = tw[2*e], w4 = tw[4*e];
        float2 w3 = cmul(w2,w1), w5 = cmul(w4,w1), w6 = cmul(w4,w2), w7 = cmul(w4,w3);
        s[base]       = y0;
        s[base+q]     = cmul(y1,w1);
        s[base+2*q]   = cmul(y2,w2);
        s[base+3*q]   = cmul(y3,w3);
        s[base+4*q]   = cmul(y4,w4);
        s[base+5*q]   = cmul(y5,w5);
        s[base+6*q]   = cmul(y6,w6);
        s[base+7*q]   = cmul(y7,w7);
        __syncthreads();
    }

    for (int p = tid; p < 4096; p += 512) {
        int k = ((p & 7) << 9) | (((p >> 3) & 7) << 6) | (((p >> 6) & 7) << 3) | ((p >> 9) & 7);
        if (!(k <= fl || k >= 4096 - fl)) s[p] = make_float2(0.f, 0.f);
    }
    __syncthreads();

    for (int logq = 0; logq <= 9; logq += 3) {
        int q = 1 << logq;
        int p = tid;
        int j = p & (q - 1);
        int base = ((p >> logq) << (logq + 3)) | j;
        int e = j << (9 - logq);
        float2 w1 = tw[e], w2 = tw[2*e], w4 = tw[4*e];
        float2 w3 = cmul(w2,w1), w5 = cmul(w4,w1), w6 = cmul(w4,w2), w7 = cmul(w4,w3);
        float2 x0 = s[base];
        float2 x1 = cmulc(s[base+q],   w1);
        float2 x2 = cmulc(s[base+2*q], w2);
        float2 x3 = cmulc(s[base+3*q], w3);
        float2 x4 = cmulc(s[base+4*q], w4);
        float2 x5 = cmulc(s[base+5*q], w5);
        float2 x6 = cmulc(s[base+6*q], w6);
        float2 x7 = cmulc(s[base+7*q], w7);
        float2 p0 = cadd(x0,x4), p1 = csub(x0,x4), p2 = cadd(x2,x6), p3 = mulposi(csub(x2,x6));
        float2 E0 = cadd(p0,p2), E1 = cadd(p1,p3), E2 = csub(p0,p2), E3 = csub(p1,p3);
        float2 q0 = cadd(x1,x5), q1 = csub(x1,x5), q2 = cadd(x3,x7), q3 = mulposi(csub(x3,x7));
        float2 O0 = cadd(q0,q2), O1 = cadd(q1,q3), O2 = csub(q0,q2), O3 = csub(q1,q3);
        float2 r1 = make_float2(RC*(O1.x-O1.y),  RC*(O1.x+O1.y));
        float2 r2 = mulposi(O2);
        float2 r3 = make_float2(-RC*(O3.x+O3.y), RC*(O3.x-O3.y));
        s[base]      = cadd(E0,O0);
        s[base+4*q]  = csub(E0,O0);
        s[base+q]    = cadd(E1,r1);
        s[base+5*q]  = csub(E1,r1);
        s[base+2*q]  = cadd(E2,r2);
        s[base+6*q]  = csub(E2,r2);
        s[base+3*q]  = cadd(E3,r3);
        s[base+7*q]  = csub(E3,r3);
        __syncthreads();
    }

    float* y0p = g_zf + roff;
    float* y1p = y0p + T;
    const float scl = 1.0f / 4096.0f;
    for (int i = tid; i < 4096; i += 512) {
        float2 v = s[i];
        y0p[i] = v.x * scl;
        y1p[i] = v.y * scl;
    }
}

// ------------------------ in_proj (cp.async 2-deep pipeline; bit-identical math) ------------------------
__global__ __launch_bounds__(256) void in_proj_kernel(int sc, int use_zf, const float* __restrict__ b_in)
{
    __shared__ float zsm[2][32][128];   // 32KB
    __shared__ float wsm[2][32][64];    // 16KB
    __shared__ float red[128][8];       // 4KB
    const float* src = use_zf ? g_zf : g_residual;
    int b = blockIdx.y, t0 = blockIdx.x * 128;
    int tid = threadIdx.x;
    int tx = tid & 31, ty = tid >> 5;

    // stage chunk k into buffer buf
    #define STAGE_IP(k, buf)                                                        \
        do {                                                                        \
            int d0_ = (k) * 32;                                                     \
            for (int i = tid; i < 1024; i += 256) {                                 \
                int dd = i >> 5, f4 = i & 31;                                       \
                cp16(&((float4*)&zsm[buf][dd][0])[f4],                              \
                     &src[((size_t)(b*D + d0_ + dd))*T + t0 + 4*f4]);               \
            }                                                                       \
            for (int i = tid; i < 512; i += 256) {                                  \
                int dd = i >> 4, f4 = i & 15;                                       \
                cp16(&((float4*)&wsm[buf][dd][0])[f4],                              \
                     &g_WiT[((size_t)sc*512 + d0_ + dd)*64 + 4*f4]);                \
            }                                                                       \
            CP_COMMIT();                                                            \
        } while (0)

    unsigned long long acc[8][2];
    #pragma unroll
    for (int i = 0; i < 8; i++) { acc[i][0] = 0ull; acc[i][1] = 0ull; }

    STAGE_IP(0, 0);
    STAGE_IP(1, 1);

    for (int k = 0; k < 16; k++) {
        if (k < 15) { CP_WAIT1(); } else { CP_WAIT0(); }
        __syncthreads();
        int buf = k & 1;
        #pragma unroll 8
        for (int dd = 0; dd < 32; dd++) {
            ulonglong2 z2 = *(const ulonglong2*)&zsm[buf][dd][4*tx];
            float4 wa = *(const float4*)&wsm[buf][dd][8*ty];
            float4 wb = *(const float4*)&wsm[buf][dd][8*ty + 4];
            unsigned long long w0 = packf2(wa.x, wa.x), w1 = packf2(wa.y, wa.y);
            unsigned long long w2 = packf2(wa.z, wa.z), w3 = packf2(wa.w, wa.w);
            unsigned long long w4 = packf2(wb.x, wb.x), w5 = packf2(wb.y, wb.y);
            unsigned long long w6 = packf2(wb.z, wb.z), w7 = packf2(wb.w, wb.w);
            fma2(acc[0][0], w0, z2.x); fma2(acc[0][1], w0, z2.y);
            fma2(acc[1][0], w1, z2.x); fma2(acc[1][1], w1, z2.y);
            fma2(acc[2][0], w2, z2.x); fma2(acc[2][1], w2, z2.y);
            fma2(acc[3][0], w3, z2.x); fma2(acc[3][1], w3, z2.y);
            fma2(acc[4][0], w4, z2.x); fma2(acc[4][1], w4, z2.y);
            fma2(acc[5][0], w5, z2.x); fma2(acc[5][1], w5, z2.y);
            fma2(acc[6][0], w6, z2.x); fma2(acc[6][1], w6, z2.y);
            fma2(acc[7][0], w7, z2.x); fma2(acc[7][1], w7, z2.y);
        }
        __syncthreads();
        if (k + 2 < 16) STAGE_IP(k + 2, buf);
    }
    #undef STAGE_IP

    float ss0 = 0.f, ss1 = 0.f, ss2 = 0.f, ss3 = 0.f;
    #pragma unroll
    for (int cc = 0; cc < 8; cc++) {
        int c = 8*ty + cc;
        float bb = b_in[sc*CD + c];
        float2 v0 = unpackf2(acc[cc][0]);
        float2 v1 = unpackf2(acc[cc][1]);
        float4 st = make_float4(v0.x + bb, v0.y + bb, v1.x + bb, v1.y + bb);
        *(float4*)&g_ze[((size_t)(b*CD + c))*T + t0 + 4*tx] = st;
        ss0 = fmaf(st.x, st.x, ss0);
        ss1 = fmaf(st.y, st.y, ss1);
        ss2 = fmaf(st.z, st.z, ss2);
        ss3 = fmaf(st.w, st.w, ss3);
    }
    red[4*tx + 0][ty] = ss0;
    red[4*tx + 1][ty] = ss1;
    red[4*tx + 2][ty] = ss2;
    red[4*tx + 3][ty] = ss3;
    __syncthreads();
    if (tid < 128) {
        float s = 0.f;
        #pragma unroll
        for (int w = 0; w < 8; w++) s += red[tid][w];
        g_inv2[b*T + t0 + tid] = 2.0f / fmaxf(sqrtf(s), 1e-12f);
    }
}

// ------------------------ nearest-code argmax (R15 exact: c-tiled + cp.async) ------------------------
__global__ __launch_bounds__(128, 4) void argmax_kernel(int sc)
{
    __shared__ float zsh[2][32][128];        // 32KB (half 0 reused for reduction scratch)
    __shared__ ulonglong2 wsh[2][2][32][8];  // 16KB
    int b = blockIdx.y, split = blockIdx.z;
    int t0 = blockIdx.x * 128;
    int tid = threadIdx.x;
    int tx = tid & 31, ty = tid >> 5;
    int jt = ty >> 1;
    int qh = (ty & 1) * 4;

    const float4* p = (const float4*)(g_cnp + (size_t)(sc*32 + split*2)*2048);

    #pragma unroll
    for (int ch = 0; ch < 2; ch++) {
        for (int i = tid; i < 1024; i += 128) {
            int c = i >> 5, f4 = i & 31;
            cp16(&((float4*)&zsh[ch][c][0])[f4],
                 (const float4*)&g_ze[((size_t)(b*CD + ch*32 + c))*T + t0 + 4*f4]);
        }
        for (int l = tid; l < 512; l += 128) {
            int sub = l >> 8, idx = l & 255;
            cp16(&((float4*)&wsh[ch][0][0][0])[l], &p[sub*512 + ch*256 + idx]);
        }
        CP_COMMIT();
    }

    unsigned long long acc[4][8];
    #pragma unroll
    for (int i = 0; i < 4; i++)
        #pragma unroll
        for (int m = 0; m < 8; m++) acc[i][m] = 0ull;

    CP_WAIT1();
    __syncthreads();

    #pragma unroll
    for (int ch = 0; ch < 2; ch++) {
        if (ch == 1) { CP_WAIT0(); __syncthreads(); }
        #pragma unroll 4
        for (int cc = 0; cc < 32; cc++) {
            float4 zf = *(const float4*)&zsh[ch][cc][4*tx];
            unsigned long long zz0 = packf2(zf.x, zf.x);
            unsigned long long zz1 = packf2(zf.y, zf.y);
            unsigned long long zz2 = packf2(zf.z, zf.z);
            unsigned long long zz3 = packf2(zf.w, zf.w);
            #pragma unroll
            for (int q = 0; q < 4; q++) {
                ulonglong2 w = wsh[ch][jt][cc][qh + q];
                fma2(acc[0][2*q], w.x, zz0); fma2(acc[0][2*q+1], w.y, zz0);
                fma2(acc[1][2*q], w.x, zz1); fma2(acc[1][2*q+1], w.y, zz1);
                fma2(acc[2][2*q], w.x, zz2); fma2(acc[2][2*q+1], w.y, zz2);
                fma2(acc[3][2*q], w.x, zz3); fma2(acc[3][2*q+1], w.y, zz3);
            }
        }
    }

    float iv[4];
    #pragma unroll
    for (int i = 0; i < 4; i++) iv[i] = g_inv2[b*T + t0 + 4*tx + i];

    int jbase = split*64 + jt*32 + qh*4;
    const float* cnn = g_cnn + sc*CS + jbase;
    float best[4]; int bi[4];
    #pragma unroll
    for (int i = 0; i < 4; i++) { best[i] = -INFINITY; bi[i] = 0; }

    #pragma unroll
    for (int q = 0; q < 4; q++) {
        float n0 = cnn[4*q + 0], n1 = cnn[4*q + 1], n2 = cnn[4*q + 2], n3 = cnn[4*q + 3];
        #pragma unroll
        for (int i = 0; i < 4; i++) {
            float2 d0 = unpackf2(acc[i][2*q]);
            float2 d1 = unpackf2(acc[i][2*q+1]);
            float s0 = fmaf(d0.x, iv[i], -n0);
            float s1 = fmaf(d0.y, iv[i], -n1);
            float s2 = fmaf(d1.x, iv[i], -n2);
            float s3 = fmaf(d1.y, iv[i], -n3);
            int j0 = jbase + 4*q;
            if (s0 > best[i]) { best[i] = s0; bi[i] = j0; }
            if (s1 > best[i]) { best[i] = s1; bi[i] = j0 + 1; }
            if (s2 > best[i]) { best[i] = s2; bi[i] = j0 + 2; }
            if (s3 > best[i]) { best[i] = s3; bi[i] = j0 + 3; }
        }
    }

    __syncthreads();
    float* rb = &zsh[0][0][0];            // [128][4] floats
    int*   ri = (int*)&zsh[0][4][0];      // [128][4] ints (disjoint)
    #pragma unroll
    for (int i = 0; i < 4; i++) {
        rb[(4*tx + i)*4 + ty] = best[i];
        ri[(4*tx + i)*4 + ty] = bi[i];
    }
    __syncthreads();
    if (tid < 128) {
        float bv = -INFINITY; int bj = 0x7fffffff;
        #pragma unroll
        for (int k = 0; k < 4; k++) {
            float v = rb[tid*4 + k];
            int ix = ri[tid*4 + k];
            if (v > bv || (v == bv && ix < bj)) { bv = v; bj = ix; }
        }
        size_t gi = (size_t)split*BT + b*T + t0 + tid;
        g_pbest[gi] = bv;
        g_pidx[gi]  = bj;
    }
}

// ------------------------ split-combine + loss + out_proj + residual (R13 exact: 512 thr) ------------------------
__global__ __launch_bounds__(512, 2) void loss_outproj_kernel(int sc, int mode,
    const float* __restrict__ cb_s, const float* __restrict__ b_out_s,
    const float* __restrict__ z, float* __restrict__ zq_out, float* __restrict__ codes_out)
{
    extern __shared__ float smem[];
    float* cbs    = smem;                 // [64][128], XOR-swizzled columns
    float* wpool2 = smem + 8192;          // [2][64*64]
    int*   scodes = (int*)wpool2;         // [128]
    float* redp   = wpool2 + 128;         // [16]
    int b = blockIdx.y, t0 = blockIdx.x * 128;
    int tid = threadIdx.x;
    int g = tid >> 8, gtid = tid & 255;
    int tx = gtid & 31, ty = gtid >> 5;

    if (tid < 128) {
        int gi = b*T + t0 + tid;
        float bv = -INFINITY; int bj = 0;
        #pragma unroll
        for (int sp = 0; sp < NSPLIT; sp++) {
            float v = g_pbest[(size_t)sp*BT + gi];
            int ix = g_pidx[(size_t)sp*BT + gi];
            if (v > bv) { bv = v; bj = ix; }
        }
        scodes[tid] = bj;
        if (codes_out)
            codes_out[((size_t)(b*NSCALES + sc))*T + t0 + tid] = (float)bj;
    }
    __syncthreads();

    for (int i = tid; i < 64*128; i += 512) {
        int tt = i >> 6, c = i & 63;
        cbs[c*128 + (tt ^ ((c & 31) << 2))] = cb_s[scodes[tt]*64 + c];
    }
    __syncthreads();

    float ls = 0.f;
    for (int i = tid; i < 64*128; i += 512) {
        int c = i >> 7, tt = i & 127;
        float d = g_ze[((size_t)(b*CD + c))*T + t0 + tt] - cbs[c*128 + (tt ^ ((c & 31) << 2))];
        ls = fmaf(d, d, ls);
    }
    #pragma unroll
    for (int o = 16; o; o >>= 1) ls += __shfl_xor_sync(~0u, ls, o);
    if ((tid & 31) == 0) redp[tid >> 5] = ls;
    __syncthreads();
    if (tid == 0) {
        float tot = 0.f;
        #pragma unroll
        for (int w = 0; w < 16; w++) tot += redp[w];
        g_partials[sc*256 + b*32 + blockIdx.x] = tot;
    }

    float* wg = wpool2 + g*4096;
    for (int k8 = 0; k8 < 4; k8++) {
        int d0 = g*256 + k8*64;
        __syncthreads();
        for (int i = gtid; i < 64*64; i += 256) {
            int c = i >> 6, dd = i & 63;
            wg[c*64 + dd] = g_WoT[((size_t)sc*64 + c)*512 + d0 + dd];
        }
        __syncthreads();

        unsigned long long acc[8][2];
        #pragma unroll
        for (int i = 0; i < 8; i++) { acc[i][0] = 0ull; acc[i][1] = 0ull; }
        #pragma unroll 8
        for (int c = 0; c < 64; c++) {
            ulonglong2 cb2 = *(const ulonglong2*)&cbs[c*128 + ((4*tx) ^ ((c & 31) << 2))];
            float4 wa = *(const float4*)&wg[c*64 + 8*ty];
            float4 wb = *(const float4*)&wg[c*64 + 8*ty + 4];
            unsigned long long w0 = packf2(wa.x, wa.x), w1 = packf2(wa.y, wa.y);
            unsigned long long w2 = packf2(wa.z, wa.z), w3 = packf2(wa.w, wa.w);
            unsigned long long w4 = packf2(wb.x, wb.x), w5 = packf2(wb.y, wb.y);
            unsigned long long w6 = packf2(wb.z, wb.z), w7 = packf2(wb.w, wb.w);
            fma2(acc[0][0], w0, cb2.x); fma2(acc[0][1], w0, cb2.y);
            fma2(acc[1][0], w1, cb2.x); fma2(acc[1][1], w1, cb2.y);
            fma2(acc[2][0], w2, cb2.x); fma2(acc[2][1], w2, cb2.y);
            fma2(acc[3][0], w3, cb2.x); fma2(acc[3][1], w3, cb2.y);
            fma2(acc[4][0], w4, cb2.x); fma2(acc[4][1], w4, cb2.y);
            fma2(acc[5][0], w5, cb2.x); fma2(acc[5][1], w5, cb2.y);
            fma2(acc[6][0], w6, cb2.x); fma2(acc[6][1], w6, cb2.y);
            fma2(acc[7][0], w7, cb2.x); fma2(acc[7][1], w7, cb2.y);
        }

        #pragma unroll
        for (int k = 0; k < 8; k++) {
            int d = d0 + 8*ty + k;
            float bb = b_out_s[d];
            float2 u0 = unpackf2(acc[k][0]);
            float2 u1 = unpackf2(acc[k][1]);
            float4 v = make_float4(u0.x + bb, u0.y + bb, u1.x + bb, u1.y + bb);
            size_t base = ((size_t)(b*D + d))*T + t0 + 4*tx;
            if (mode == 0) {
                float4 zv = *(const float4*)&z[base];
                float4 r = make_float4(zv.x - v.x, zv.y - v.y, zv.z - v.z, zv.w - v.w);
                *(float4*)&g_residual[base] = r;
            } else if (mode == 1) {
                float4 r = *(const float4*)&g_residual[base];
                r.x -= v.x; r.y -= v.y; r.z -= v.z; r.w -= v.w;
                *(float4*)&g_residual[base] = r;
            } else {
                float4 zv = *(const float4*)&z[base];
                float4 r = *(const float4*)&g_residual[base];
                float4 o = make_float4(zv.x - r.x + v.x, zv.y - r.y + v.y,
                                       zv.z - r.z + v.z, zv.w - r.w + v.w);
                *(float4*)&zq_out[base] = o;
            }
        }
    }
}

// ------------------------ final loss reduce ------------------------
__global__ void reduce_loss_kernel(float* __restrict__ out_loss)
{
    __shared__ float s[1024];
    int tid = threadIdx.x;
    float v = 0.f;
    for (int i = tid; i < NSCALES*256; i += 1024) v += g_partials[i];
    s[tid] = v;
    __syncthreads();
    for (int h = 512; h; h >>= 1) {
        if (tid < h) s[tid] += s[tid + h];
        __syncthreads();
    }
    if (tid == 0) {
        float m = s[0] / LOSS_MEAN_DENOM;
        out_loss[0] = m;
        out_loss[1] = m;
    }
}

// ------------------------ launch ------------------------
extern "C" void kernel_launch(void* const* d_in, const int* in_sizes, int n_in,
                              void* d_out, int out_size)
{
    const float* z     = (const float*)d_in[0];
    const float* v_in  = (const float*)d_in[1];
    const float* g_in  = (const float*)d_in[2];
    const float* b_in  = (const float*)d_in[3];
    const float* cb    = (const float*)d_in[4];
    const float* v_out = (const float*)d_in[5];
    const float* g_out = (const float*)d_in[6];
    const float* b_out = (const float*)d_in[7];
    float* out = (float*)d_out;

    bool full = out_size >= (LOSS_OFF + 2);
    float* codes_out = full ? (out + ZQ_ELEMS) : nullptr;

    const int SMEM_LO = 65536;
    cudaFuncSetAttribute(loss_outproj_kernel,
                         cudaFuncAttributeMaxDynamicSharedMemorySize, SMEM_LO);

    prep_weights_kernel<<<NSCALES*1600, 128>>>(v_in, g_in, v_out, g_out, cb);

    const int scales[NSCALES] = {4, 2, 1, 1};
    for (int i = 0; i < NSCALES; i++) {
        int s = scales[i];
        int use_zf = (s > 1) ? 1 : 0;
        if (use_zf) {
            int fl = 2049 / s;
            fft_filter_kernel<<<NROWS/2, 512>>>(z, (i == 0) ? 1 : 0, fl);
        }
        in_proj_kernel<<<dim3(T/128, B), 256>>>(i, use_zf, b_in);
        argmax_kernel<<<dim3(T/128, B, NSPLIT), 128>>>(i);
        int mode = (i == 0) ? 0 : ((i == NSCALES-1) ? 2 : 1);
        loss_outproj_kernel<<<dim3(T/128, B), 512, SMEM_LO>>>(i, mode, cb + (size_t)i*CS*CD,
                                                              b_out + i*D, z, out, codes_out);
    }
    if (full) reduce_loss_kernel<<<1, 1024>>>(out + LOSS_OFF);
}

// round 17
// speedup vs baseline: 1.1226x; 1.0062x over previous
#include <cuda_runtime.h>
#include <math.h>

#define B 8
#define D 512
#define T 4096
#define CD 64
#define CS 1024
#define NSCALES 4
#define NSPLIT 16
#define NROWS (B*D)
#define BT (B*T)
#define ZQ_ELEMS (B*D*T)                  // 16777216
#define CODES_ELEMS (B*NSCALES*T)         // 131072
#define LOSS_OFF (ZQ_ELEMS + CODES_ELEMS)
#define LOSS_MEAN_DENOM 2097152.0f        // B*CD*T

// ------------------------ scratch ------------------------
__device__ float g_residual[ZQ_ELEMS];        // 64MB
__device__ float g_zf[ZQ_ELEMS];              // 64MB (band-filtered residual)
__device__ float g_ze[B*CD*T];                // 8MB
__device__ float g_inv2[BT];                  // 2/||z_e(t)||
__device__ float g_WiT[NSCALES*D*CD];         // weight-normed in-proj, [d][c]
__device__ float g_WoT[NSCALES*CD*D];         // weight-normed out-proj, [c][d]
__device__ float g_cnp[NSCALES*CS*CD];        // normalized codebook, tile/pair-packed
__device__ float g_cnn[NSCALES*CS];           // ||cn_j||^2
__device__ float g_pbest[NSPLIT*BT];
__device__ int   g_pidx [NSPLIT*BT];
__device__ float g_partials[NSCALES*256];

// ------------------------ f32x2 helpers ------------------------
__device__ __forceinline__ void fma2(unsigned long long& acc,
                                     unsigned long long a, unsigned long long b) {
    asm("fma.rn.f32x2 %0, %1, %2, %0;" : "+l"(acc) : "l"(a), "l"(b));
}
__device__ __forceinline__ unsigned long long packf2(float lo, float hi) {
    unsigned long long r;
    asm("mov.b64 %0, {%1, %2};" : "=l"(r) : "f"(lo), "f"(hi));
    return r;
}
__device__ __forceinline__ float2 unpackf2(unsigned long long v) {
    float lo, hi;
    asm("mov.b64 {%0, %1}, %2;" : "=f"(lo), "=f"(hi) : "l"(v));
    return make_float2(lo, hi);
}

// ------------------------ cp.async helpers ------------------------
__device__ __forceinline__ void cp16(void* dst_smem, const void* src) {
    unsigned u = (unsigned)__cvta_generic_to_shared(dst_smem);
    asm volatile("cp.async.cg.shared.global [%0], [%1], 16;" :: "r"(u), "l"(src));
}
#define CP_COMMIT() asm volatile("cp.async.commit_group;" ::: "memory")
#define CP_WAIT1()  asm volatile("cp.async.wait_group 1;" ::: "memory")
#define CP_WAIT0()  asm volatile("cp.async.wait_group 0;" ::: "memory")

// ------------------------ complex helpers ------------------------
__device__ __forceinline__ float2 cadd(float2 a, float2 b){return make_float2(a.x+b.x, a.y+b.y);}
__device__ __forceinline__ float2 csub(float2 a, float2 b){return make_float2(a.x-b.x, a.y-b.y);}
__device__ __forceinline__ float2 cmul(float2 a, float2 b){
    return make_float2(a.x*b.x - a.y*b.y, a.x*b.y + a.y*b.x);}
__device__ __forceinline__ float2 cmulc(float2 a, float2 b){
    return make_float2(a.x*b.x + a.y*b.y, a.y*b.x - a.x*b.y);}
__device__ __forceinline__ float2 mulnegi(float2 a){return make_float2(a.y, -a.x);}
__device__ __forceinline__ float2 mulposi(float2 a){return make_float2(-a.y, a.x);}

// ------------------------ weight prep (R3 exact) ------------------------
__global__ void prep_weights_kernel(const float* __restrict__ v_in,
                                    const float* __restrict__ g_in,
                                    const float* __restrict__ v_out,
                                    const float* __restrict__ g_out,
                                    const float* __restrict__ codebook)
{
    int blk = blockIdx.x;
    int sc = blk / 1600;
    int r  = blk % 1600;
    int tid = threadIdx.x;
    __shared__ float red[4];

    const float* src; int n; float g; int kind;
    if (r < 64) { src = v_in + (size_t)(sc*64 + r)*512; n = 512; g = g_in[sc*64 + r]; kind = 0; }
    else if (r < 576) { int d = r-64; src = v_out + (size_t)(sc*512 + d)*64; n = 64; g = g_out[sc*512 + d]; kind = 1; }
    else { src = codebook + (size_t)(sc*1024 + (r-576))*64; n = 64; g = 1.0f; kind = 2; }

    float ss = 0.f;
    for (int i = tid; i < n; i += 128) { float v = src[i]; ss = fmaf(v, v, ss); }
    #pragma unroll
    for (int o = 16; o; o >>= 1) ss += __shfl_xor_sync(~0u, ss, o);
    if ((tid & 31) == 0) red[tid >> 5] = ss;
    __syncthreads();
    float tot = red[0] + red[1] + red[2] + red[3];
    float inv = g / fmaxf(sqrtf(tot), 1e-12f);

    if (kind == 0) {
        int c = r;
        for (int i = tid; i < n; i += 128)
            g_WiT[((size_t)sc*512 + i)*64 + c] = src[i] * inv;
    } else if (kind == 1) {
        int d = r - 64;
        for (int i = tid; i < n; i += 128)
            g_WoT[((size_t)sc*64 + i)*512 + d] = src[i] * inv;
    } else {
        int j = r - 576;
        float ss2 = 0.f;
        for (int i = tid; i < n; i += 128) {
            float v = src[i] * inv;
            size_t fidx = ((((size_t)(sc*32 + (j>>5))*64 + i)*8 + ((j&31)>>2))*4) + (j&3);
            g_cnp[fidx] = v;
            ss2 = fmaf(v, v, ss2);
        }
        #pragma unroll
        for (int o = 16; o; o >>= 1) ss2 += __shfl_xor_sync(~0u, ss2, o);
        __syncthreads();
        if ((tid & 31) == 0) red[tid >> 5] = ss2;
        __syncthreads();
        if (tid == 0) g_cnn[sc*1024 + j] = red[0] + red[1] + red[2] + red[3];
    }
}

// ------------------------ FFT band filter (radix-8, R11 exact) ------------------------
__global__ __launch_bounds__(512) void fft_filter_kernel(const float* __restrict__ zsrc, int use_z, int fl)
{
    __shared__ float2 s[4096];
    __shared__ float2 tw[2048];
    const float* src = use_z ? zsrc : g_residual;
    size_t roff = (size_t)blockIdx.x * 2 * T;
    const float* x0g = src + roff;
    const float* x1g = x0g + T;
    int tid = threadIdx.x;
    const float RC = 0.70710678118654752f;

    for (int i = tid; i < 4096; i += 512) s[i] = make_float2(x0g[i], x1g[i]);
    for (int k = tid; k < 2048; k += 512) {
        float sv, cv;
        sincospif((float)k * (-1.0f/2048.0f), &sv, &cv);
        tw[k] = make_float2(cv, sv);
    }
    __syncthreads();

    for (int logq = 9; logq >= 0; logq -= 3) {
        int q = 1 << logq;
        int p = tid;
        int j = p & (q - 1);
        int base = ((p >> logq) << (logq + 3)) | j;
        float2 x0 = s[base],       x1 = s[base+q],   x2 = s[base+2*q], x3 = s[base+3*q];
        float2 x4 = s[base+4*q],   x5 = s[base+5*q], x6 = s[base+6*q], x7 = s[base+7*q];
        float2 p0 = cadd(x0,x4), p1 = csub(x0,x4), p2 = cadd(x2,x6), p3 = mulnegi(csub(x2,x6));
        float2 E0 = cadd(p0,p2), E1 = cadd(p1,p3), E2 = csub(p0,p2), E3 = csub(p1,p3);
        float2 q0 = cadd(x1,x5), q1 = csub(x1,x5), q2 = cadd(x3,x7), q3 = mulnegi(csub(x3,x7));
        float2 O0 = cadd(q0,q2), O1 = cadd(q1,q3), O2 = csub(q0,q2), O3 = csub(q1,q3);
        float2 r1 = make_float2(RC*(O1.x+O1.y), RC*(O1.y-O1.x));
        float2 r2 = mulnegi(O2);
        float2 r3 = make_float2(RC*(O3.y-O3.x), -RC*(O3.x+O3.y));
        float2 y0 = cadd(E0,O0), y4 = csub(E0,O0);
        float2 y1 = cadd(E1,r1), y5 = csub(E1,r1);
        float2 y2 = cadd(E2,r2), y6 = csub(E2,r2);
        float2 y3 = cadd(E3,r3), y7 = csub(E3,r3);
        int e = j << (9 - logq);
        float2 w1 = tw[e], w2 = tw[2*e], w4 = tw[4*e];
        float2 w3 = cmul(w2,w1), w5 = cmul(w4,w1), w6 = cmul(w4,w2), w7 = cmul(w4,w3);
        s[base]       = y0;
        s[base+q]     = cmul(y1,w1);
        s[base+2*q]   = cmul(y2,w2);
        s[base+3*q]   = cmul(y3,w3);
        s[base+4*q]   = cmul(y4,w4);
        s[base+5*q]   = cmul(y5,w5);
        s[base+6*q]   = cmul(y6,w6);
        s[base+7*q]   = cmul(y7,w7);
        __syncthreads();
    }

    for (int p = tid; p < 4096; p += 512) {
        int k = ((p & 7) << 9) | (((p >> 3) & 7) << 6) | (((p >> 6) & 7) << 3) | ((p >> 9) & 7);
        if (!(k <= fl || k >= 4096 - fl)) s[p] = make_float2(0.f, 0.f);
    }
    __syncthreads();

    for (int logq = 0; logq <= 9; logq += 3) {
        int q = 1 << logq;
        int p = tid;
        int j = p & (q - 1);
        int base = ((p >> logq) << (logq + 3)) | j;
        int e = j << (9 - logq);
        float2 w1 = tw[e], w2 = tw[2*e], w4 = tw[4*e];
        float2 w3 = cmul(w2,w1), w5 = cmul(w4,w1), w6 = cmul(w4,w2), w7 = cmul(w4,w3);
        float2 x0 = s[base];
        float2 x1 = cmulc(s[base+q],   w1);
        float2 x2 = cmulc(s[base+2*q], w2);
        float2 x3 = cmulc(s[base+3*q], w3);
        float2 x4 = cmulc(s[base+4*q], w4);
        float2 x5 = cmulc(s[base+5*q], w5);
        float2 x6 = cmulc(s[base+6*q], w6);
        float2 x7 = cmulc(s[base+7*q], w7);
        float2 p0 = cadd(x0,x4), p1 = csub(x0,x4), p2 = cadd(x2,x6), p3 = mulposi(csub(x2,x6));
        float2 E0 = cadd(p0,p2), E1 = cadd(p1,p3), E2 = csub(p0,p2), E3 = csub(p1,p3);
        float2 q0 = cadd(x1,x5), q1 = csub(x1,x5), q2 = cadd(x3,x7), q3 = mulposi(csub(x3,x7));
        float2 O0 = cadd(q0,q2), O1 = cadd(q1,q3), O2 = csub(q0,q2), O3 = csub(q1,q3);
        float2 r1 = make_float2(RC*(O1.x-O1.y),  RC*(O1.x+O1.y));
        float2 r2 = mulposi(O2);
        float2 r3 = make_float2(-RC*(O3.x+O3.y), RC*(O3.x-O3.y));
        s[base]      = cadd(E0,O0);
        s[base+4*q]  = csub(E0,O0);
        s[base+q]    = cadd(E1,r1);
        s[base+5*q]  = csub(E1,r1);
        s[base+2*q]  = cadd(E2,r2);
        s[base+6*q]  = csub(E2,r2);
        s[base+3*q]  = cadd(E3,r3);
        s[base+7*q]  = csub(E3,r3);
        __syncthreads();
    }

    float* y0p = g_zf + roff;
    float* y1p = y0p + T;
    const float scl = 1.0f / 4096.0f;
    for (int i = tid; i < 4096; i += 512) {
        float2 v = s[i];
        y0p[i] = v.x * scl;
        y1p[i] = v.y * scl;
    }
}

// ------------------------ in_proj (R16 exact: cp.async 2-deep pipeline) ------------------------
__global__ __launch_bounds__(256) void in_proj_kernel(int sc, int use_zf, const float* __restrict__ b_in)
{
    __shared__ float zsm[2][32][128];   // 32KB
    __shared__ float wsm[2][32][64];    // 16KB
    __shared__ float red[128][8];       // 4KB
    const float* src = use_zf ? g_zf : g_residual;
    int b = blockIdx.y, t0 = blockIdx.x * 128;
    int tid = threadIdx.x;
    int tx = tid & 31, ty = tid >> 5;

    #define STAGE_IP(k, buf)                                                        \
        do {                                                                        \
            int d0_ = (k) * 32;                                                     \
            for (int i = tid; i < 1024; i += 256) {                                 \
                int dd = i >> 5, f4 = i & 31;                                       \
                cp16(&((float4*)&zsm[buf][dd][0])[f4],                              \
                     &src[((size_t)(b*D + d0_ + dd))*T + t0 + 4*f4]);               \
            }                                                                       \
            for (int i = tid; i < 512; i += 256) {                                  \
                int dd = i >> 4, f4 = i & 15;                                       \
                cp16(&((float4*)&wsm[buf][dd][0])[f4],                              \
                     &g_WiT[((size_t)sc*512 + d0_ + dd)*64 + 4*f4]);                \
            }                                                                       \
            CP_COMMIT();                                                            \
        } while (0)

    unsigned long long acc[8][2];
    #pragma unroll
    for (int i = 0; i < 8; i++) { acc[i][0] = 0ull; acc[i][1] = 0ull; }

    STAGE_IP(0, 0);
    STAGE_IP(1, 1);

    for (int k = 0; k < 16; k++) {
        if (k < 15) { CP_WAIT1(); } else { CP_WAIT0(); }
        __syncthreads();
        int buf = k & 1;
        #pragma unroll 8
        for (int dd = 0; dd < 32; dd++) {
            ulonglong2 z2 = *(const ulonglong2*)&zsm[buf][dd][4*tx];
            float4 wa = *(const float4*)&wsm[buf][dd][8*ty];
            float4 wb = *(const float4*)&wsm[buf][dd][8*ty + 4];
            unsigned long long w0 = packf2(wa.x, wa.x), w1 = packf2(wa.y, wa.y);
            unsigned long long w2 = packf2(wa.z, wa.z), w3 = packf2(wa.w, wa.w);
            unsigned long long w4 = packf2(wb.x, wb.x), w5 = packf2(wb.y, wb.y);
            unsigned long long w6 = packf2(wb.z, wb.z), w7 = packf2(wb.w, wb.w);
            fma2(acc[0][0], w0, z2.x); fma2(acc[0][1], w0, z2.y);
            fma2(acc[1][0], w1, z2.x); fma2(acc[1][1], w1, z2.y);
            fma2(acc[2][0], w2, z2.x); fma2(acc[2][1], w2, z2.y);
            fma2(acc[3][0], w3, z2.x); fma2(acc[3][1], w3, z2.y);
            fma2(acc[4][0], w4, z2.x); fma2(acc[4][1], w4, z2.y);
            fma2(acc[5][0], w5, z2.x); fma2(acc[5][1], w5, z2.y);
            fma2(acc[6][0], w6, z2.x); fma2(acc[6][1], w6, z2.y);
            fma2(acc[7][0], w7, z2.x); fma2(acc[7][1], w7, z2.y);
        }
        __syncthreads();
        if (k + 2 < 16) STAGE_IP(k + 2, buf);
    }
    #undef STAGE_IP

    float ss0 = 0.f, ss1 = 0.f, ss2 = 0.f, ss3 = 0.f;
    #pragma unroll
    for (int cc = 0; cc < 8; cc++) {
        int c = 8*ty + cc;
        float bb = b_in[sc*CD + c];
        float2 v0 = unpackf2(acc[cc][0]);
        float2 v1 = unpackf2(acc[cc][1]);
        float4 st = make_float4(v0.x + bb, v0.y + bb, v1.x + bb, v1.y + bb);
        *(float4*)&g_ze[((size_t)(b*CD + c))*T + t0 + 4*tx] = st;
        ss0 = fmaf(st.x, st.x, ss0);
        ss1 = fmaf(st.y, st.y, ss1);
        ss2 = fmaf(st.z, st.z, ss2);
        ss3 = fmaf(st.w, st.w, ss3);
    }
    red[4*tx + 0][ty] = ss0;
    red[4*tx + 1][ty] = ss1;
    red[4*tx + 2][ty] = ss2;
    red[4*tx + 3][ty] = ss3;
    __syncthreads();
    if (tid < 128) {
        float s = 0.f;
        #pragma unroll
        for (int w = 0; w < 8; w++) s += red[tid][w];
        g_inv2[b*T + t0 + tid] = 2.0f / fmaxf(sqrtf(s), 1e-12f);
    }
}

// ------------------------ nearest-code argmax (R15 exact: c-tiled + cp.async) ------------------------
__global__ __launch_bounds__(128, 4) void argmax_kernel(int sc)
{
    __shared__ float zsh[2][32][128];        // 32KB (half 0 reused for reduction scratch)
    __shared__ ulonglong2 wsh[2][2][32][8];  // 16KB
    int b = blockIdx.y, split = blockIdx.z;
    int t0 = blockIdx.x * 128;
    int tid = threadIdx.x;
    int tx = tid & 31, ty = tid >> 5;
    int jt = ty >> 1;
    int qh = (ty & 1) * 4;

    const float4* p = (const float4*)(g_cnp + (size_t)(sc*32 + split*2)*2048);

    #pragma unroll
    for (int ch = 0; ch < 2; ch++) {
        for (int i = tid; i < 1024; i += 128) {
            int c = i >> 5, f4 = i & 31;
            cp16(&((float4*)&zsh[ch][c][0])[f4],
                 (const float4*)&g_ze[((size_t)(b*CD + ch*32 + c))*T + t0 + 4*f4]);
        }
        for (int l = tid; l < 512; l += 128) {
            int sub = l >> 8, idx = l & 255;
            cp16(&((float4*)&wsh[ch][0][0][0])[l], &p[sub*512 + ch*256 + idx]);
        }
        CP_COMMIT();
    }

    unsigned long long acc[4][8];
    #pragma unroll
    for (int i = 0; i < 4; i++)
        #pragma unroll
        for (int m = 0; m < 8; m++) acc[i][m] = 0ull;

    CP_WAIT1();
    __syncthreads();

    #pragma unroll
    for (int ch = 0; ch < 2; ch++) {
        if (ch == 1) { CP_WAIT0(); __syncthreads(); }
        #pragma unroll 4
        for (int cc = 0; cc < 32; cc++) {
            float4 zf = *(const float4*)&zsh[ch][cc][4*tx];
            unsigned long long zz0 = packf2(zf.x, zf.x);
            unsigned long long zz1 = packf2(zf.y, zf.y);
            unsigned long long zz2 = packf2(zf.z, zf.z);
            unsigned long long zz3 = packf2(zf.w, zf.w);
            #pragma unroll
            for (int q = 0; q < 4; q++) {
                ulonglong2 w = wsh[ch][jt][cc][qh + q];
                fma2(acc[0][2*q], w.x, zz0); fma2(acc[0][2*q+1], w.y, zz0);
                fma2(acc[1][2*q], w.x, zz1); fma2(acc[1][2*q+1], w.y, zz1);
                fma2(acc[2][2*q], w.x, zz2); fma2(acc[2][2*q+1], w.y, zz2);
                fma2(acc[3][2*q], w.x, zz3); fma2(acc[3][2*q+1], w.y, zz3);
            }
        }
    }

    float iv[4];
    #pragma unroll
    for (int i = 0; i < 4; i++) iv[i] = g_inv2[b*T + t0 + 4*tx + i];

    int jbase = split*64 + jt*32 + qh*4;
    const float* cnn = g_cnn + sc*CS + jbase;
    float best[4]; int bi[4];
    #pragma unroll
    for (int i = 0; i < 4; i++) { best[i] = -INFINITY; bi[i] = 0; }

    #pragma unroll
    for (int q = 0; q < 4; q++) {
        float n0 = cnn[4*q + 0], n1 = cnn[4*q + 1], n2 = cnn[4*q + 2], n3 = cnn[4*q + 3];
        #pragma unroll
        for (int i = 0; i < 4; i++) {
            float2 d0 = unpackf2(acc[i][2*q]);
            float2 d1 = unpackf2(acc[i][2*q+1]);
            float s0 = fmaf(d0.x, iv[i], -n0);
            float s1 = fmaf(d0.y, iv[i], -n1);
            float s2 = fmaf(d1.x, iv[i], -n2);
            float s3 = fmaf(d1.y, iv[i], -n3);
            int j0 = jbase + 4*q;
            if (s0 > best[i]) { best[i] = s0; bi[i] = j0; }
            if (s1 > best[i]) { best[i] = s1; bi[i] = j0 + 1; }
            if (s2 > best[i]) { best[i] = s2; bi[i] = j0 + 2; }
            if (s3 > best[i]) { best[i] = s3; bi[i] = j0 + 3; }
        }
    }

    __syncthreads();
    float* rb = &zsh[0][0][0];            // [128][4] floats
    int*   ri = (int*)&zsh[0][4][0];      // [128][4] ints (disjoint)
    #pragma unroll
    for (int i = 0; i < 4; i++) {
        rb[(4*tx + i)*4 + ty] = best[i];
        ri[(4*tx + i)*4 + ty] = bi[i];
    }
    __syncthreads();
    if (tid < 128) {
        float bv = -INFINITY; int bj = 0x7fffffff;
        #pragma unroll
        for (int k = 0; k < 4; k++) {
            float v = rb[tid*4 + k];
            int ix = ri[tid*4 + k];
            if (v > bv || (v == bv && ix < bj)) { bv = v; bj = ix; }
        }
        size_t gi = (size_t)split*BT + b*T + t0 + tid;
        g_pbest[gi] = bv;
        g_pidx[gi]  = bj;
    }
}

// ------------------------ split-combine + loss + out_proj + residual ------------------------
// 512 thr, two d-groups (R13 math) + cp.async W prefetch: chunks 0,1 issued at kernel
// entry (fly during combine/gather/loss), 2-deep rotation thereafter.
// smem: cbs 8192f | wpool 2g x 2buf x 4096f | scodes 128i | redp 16f = 24736 floats.
__global__ __launch_bounds__(512, 2) void loss_outproj_kernel(int sc, int mode,
    const float* __restrict__ cb_s, const float* __restrict__ b_out_s,
    const float* __restrict__ z, float* __restrict__ zq_out, float* __restrict__ codes_out)
{
    extern __shared__ float smem[];
    float* cbs    = smem;                 // [64][128], XOR-swizzled columns
    float* wpool  = smem + 8192;          // [2 groups][2 bufs][4096]
    int*   scodes = (int*)(smem + 24576); // [128]
    float* redp   = smem + 24576 + 128;   // [16]
    int b = blockIdx.y, t0 = blockIdx.x * 128;
    int tid = threadIdx.x;
    int g = tid >> 8, gtid = tid & 255;
    int tx = gtid & 31, ty = gtid >> 5;

    #define STAGE_LO(k, buf)                                                        \
        do {                                                                        \
            int d0_ = g*256 + (k)*64;                                               \
            float4* wdst = (float4*)(wpool + g*8192 + (buf)*4096);                  \
            for (int i = gtid; i < 1024; i += 256) {                                \
                int c = i >> 4, f4 = i & 15;                                        \
                cp16(&wdst[i], &g_WoT[((size_t)sc*64 + c)*512 + d0_ + 4*f4]);       \
            }                                                                       \
            CP_COMMIT();                                                            \
        } while (0)

    // prefetch W chunks 0,1 immediately — they fly during combine/gather/loss
    STAGE_LO(0, 0);
    STAGE_LO(1, 1);

    if (tid < 128) {
        int gi = b*T + t0 + tid;
        float bv = -INFINITY; int bj = 0;
        #pragma unroll
        for (int sp = 0; sp < NSPLIT; sp++) {
            float v = g_pbest[(size_t)sp*BT + gi];
            int ix = g_pidx[(size_t)sp*BT + gi];
            if (v > bv) { bv = v; bj = ix; }
        }
        scodes[tid] = bj;
        if (codes_out)
            codes_out[((size_t)(b*NSCALES + sc))*T + t0 + tid] = (float)bj;
    }
    __syncthreads();

    for (int i = tid; i < 64*128; i += 512) {
        int tt = i >> 6, c = i & 63;
        cbs[c*128 + (tt ^ ((c & 31) << 2))] = cb_s[scodes[tt]*64 + c];
    }
    __syncthreads();

    float ls = 0.f;
    for (int i = tid; i < 64*128; i += 512) {
        int c = i >> 7, tt = i & 127;
        float d = g_ze[((size_t)(b*CD + c))*T + t0 + tt] - cbs[c*128 + (tt ^ ((c & 31) << 2))];
        ls = fmaf(d, d, ls);
    }
    #pragma unroll
    for (int o = 16; o; o >>= 1) ls += __shfl_xor_sync(~0u, ls, o);
    if ((tid & 31) == 0) redp[tid >> 5] = ls;
    __syncthreads();
    if (tid == 0) {
        float tot = 0.f;
        #pragma unroll
        for (int w = 0; w < 16; w++) tot += redp[w];
        g_partials[sc*256 + b*32 + blockIdx.x] = tot;
    }

    for (int k8 = 0; k8 < 4; k8++) {
        int d0 = g*256 + k8*64;
        if (k8 < 3) { CP_WAIT1(); } else { CP_WAIT0(); }
        __syncthreads();
        const float* wg = wpool + g*8192 + (k8 & 1)*4096;

        unsigned long long acc[8][2];
        #pragma unroll
        for (int i = 0; i < 8; i++) { acc[i][0] = 0ull; acc[i][1] = 0ull; }
        #pragma unroll 8
        for (int c = 0; c < 64; c++) {
            ulonglong2 cb2 = *(const ulonglong2*)&cbs[c*128 + ((4*tx) ^ ((c & 31) << 2))];
            float4 wa = *(const float4*)&wg[c*64 + 8*ty];
            float4 wb = *(const float4*)&wg[c*64 + 8*ty + 4];
            unsigned long long w0 = packf2(wa.x, wa.x), w1 = packf2(wa.y, wa.y);
            unsigned long long w2 = packf2(wa.z, wa.z), w3 = packf2(wa.w, wa.w);
            unsigned long long w4 = packf2(wb.x, wb.x), w5 = packf2(wb.y, wb.y);
            unsigned long long w6 = packf2(wb.z, wb.z), w7 = packf2(wb.w, wb.w);
            fma2(acc[0][0], w0, cb2.x); fma2(acc[0][1], w0, cb2.y);
            fma2(acc[1][0], w1, cb2.x); fma2(acc[1][1], w1, cb2.y);
            fma2(acc[2][0], w2, cb2.x); fma2(acc[2][1], w2, cb2.y);
            fma2(acc[3][0], w3, cb2.x); fma2(acc[3][1], w3, cb2.y);
            fma2(acc[4][0], w4, cb2.x); fma2(acc[4][1], w4, cb2.y);
            fma2(acc[5][0], w5, cb2.x); fma2(acc[5][1], w5, cb2.y);
            fma2(acc[6][0], w6, cb2.x); fma2(acc[6][1], w6, cb2.y);
            fma2(acc[7][0], w7, cb2.x); fma2(acc[7][1], w7, cb2.y);
        }

        #pragma unroll
        for (int k = 0; k < 8; k++) {
            int d = d0 + 8*ty + k;
            float bb = b_out_s[d];
            float2 u0 = unpackf2(acc[k][0]);
            float2 u1 = unpackf2(acc[k][1]);
            float4 v = make_float4(u0.x + bb, u0.y + bb, u1.x + bb, u1.y + bb);
            size_t base = ((size_t)(b*D + d))*T + t0 + 4*tx;
            if (mode == 0) {
                float4 zv = *(const float4*)&z[base];
                float4 r = make_float4(zv.x - v.x, zv.y - v.y, zv.z - v.z, zv.w - v.w);
                *(float4*)&g_residual[base] = r;
            } else if (mode == 1) {
                float4 r = *(const float4*)&g_residual[base];
                r.x -= v.x; r.y -= v.y; r.z -= v.z; r.w -= v.w;
                *(float4*)&g_residual[base] = r;
            } else {
                float4 zv = *(const float4*)&z[base];
                float4 r = *(const float4*)&g_residual[base];
                float4 o = make_float4(zv.x - r.x + v.x, zv.y - r.y + v.y,
                                       zv.z - r.z + v.z, zv.w - r.w + v.w);
                *(float4*)&zq_out[base] = o;
            }
        }
        __syncthreads();                       // all reads of this buf done
        if (k8 + 2 < 4) STAGE_LO(k8 + 2, k8 & 1);
    }
    #undef STAGE_LO
}

// ------------------------ final loss reduce ------------------------
__global__ void reduce_loss_kernel(float* __restrict__ out_loss)
{
    __shared__ float s[1024];
    int tid = threadIdx.x;
    float v = 0.f;
    for (int i = tid; i < NSCALES*256; i += 1024) v += g_partials[i];
    s[tid] = v;
    __syncthreads();
    for (int h = 512; h; h >>= 1) {
        if (tid < h) s[tid] += s[tid + h];
        __syncthreads();
    }
    if (tid == 0) {
        float m = s[0] / LOSS_MEAN_DENOM;
        out_loss[0] = m;
        out_loss[1] = m;
    }
}

// ------------------------ launch ------------------------
extern "C" void kernel_launch(void* const* d_in, const int* in_sizes, int n_in,
                              void* d_out, int out_size)
{
    const float* z     = (const float*)d_in[0];
    const float* v_in  = (const float*)d_in[1];
    const float* g_in  = (const float*)d_in[2];
    const float* b_in  = (const float*)d_in[3];
    const float* cb    = (const float*)d_in[4];
    const float* v_out = (const float*)d_in[5];
    const float* g_out = (const float*)d_in[6];
    const float* b_out = (const float*)d_in[7];
    float* out = (float*)d_out;

    bool full = out_size >= (LOSS_OFF + 2);
    float* codes_out = full ? (out + ZQ_ELEMS) : nullptr;

    const int SMEM_LO = (24576 + 144) * 4;   // 98880 bytes
    cudaFuncSetAttribute(loss_outproj_kernel,
                         cudaFuncAttributeMaxDynamicSharedMemorySize, SMEM_LO);

    prep_weights_kernel<<<NSCALES*1600, 128>>>(v_in, g_in, v_out, g_out, cb);

    const int scales[NSCALES] = {4, 2, 1, 1};
    for (int i = 0; i < NSCALES; i++) {
        int s = scales[i];
        int use_zf = (s > 1) ? 1 : 0;
        if (use_zf) {
            int fl = 2049 / s;
            fft_filter_kernel<<<NROWS/2, 512>>>(z, (i == 0) ? 1 : 0, fl);
        }
        in_proj_kernel<<<dim3(T/128, B), 256>>>(i, use_zf, b_in);
        argmax_kernel<<<dim3(T/128, B, NSPLIT), 128>>>(i);
        int mode = (i == 0) ? 0 : ((i == NSCALES-1) ? 2 : 1);
        loss_outproj_kernel<<<dim3(T/128, B), 512, SMEM_LO>>>(i, mode, cb + (size_t)i*CS*CD,
                                                              b_out + i*D, z, out, codes_out);
    }
    if (full) reduce_loss_kernel<<<1, 1024>>>(out + LOSS_OFF);
}